// round 4
// baseline (speedup 1.0000x reference)
#include <cuda_runtime.h>
#include <cuda_bf16.h>
#include <cstdint>

// Problem constants
#define B_ 8
#define C_ 256
#define H_ 25
#define W_ 25
#define N_ 256
#define OUT_ 7
#define NBIN 49
#define IN_ 12544   // C*7*7
#define DFC_ 1024
#define FCC_ 512
#define SS_ (25.0f/255.0f)
#define TRANS_STD_ 0.1f

// Scratch (device globals — no allocation allowed)
__device__ float g_xt[B_*H_*W_*C_];    // (B,H,W,C)
__device__ float g_p0[N_*IN_];
__device__ float g_h1[N_*DFC_];
__device__ float g_h2[N_*DFC_];
__device__ float g_off[N_*2*NBIN];
__device__ float g_p1[N_*IN_];
__device__ float g_f1[N_*FCC_];
__device__ float g_f2[N_*FCC_];
__device__ float g_part[16*N_*FCC_];   // split-K partials: 16*256*512 == 8*256*1024

// ---------------------------------------------------------------------------
// Transpose x (B,C,H,W) -> xt (B,H*W,C)
// ---------------------------------------------------------------------------
__global__ void transpose_kernel(const float* __restrict__ x, float* __restrict__ xt) {
    __shared__ float tile[32][33];
    int b  = blockIdx.z;
    int s0 = blockIdx.x * 32;
    int c0 = blockIdx.y * 32;
    int tx = threadIdx.x, ty = threadIdx.y; // 32 x 8
    const int HW = H_*W_;
    #pragma unroll
    for (int i = ty; i < 32; i += 8) {
        int c = c0 + i, s = s0 + tx;
        if (c < C_ && s < HW) tile[i][tx] = x[(b*C_ + c)*HW + s];
    }
    __syncthreads();
    #pragma unroll
    for (int i = ty; i < 32; i += 8) {
        int s = s0 + i, c = c0 + tx;
        if (s < HW && c < C_) xt[(b*HW + s)*C_ + c] = tile[tx][i];
    }
}

// ---------------------------------------------------------------------------
// Deformable ROI pool, factorized: valid/weights/count all separate into
// x-terms (depend only on sample j) and y-terms (only on i). Aggregate the
// 4 x-samples into <=8 unique columns and likewise for y, then gather only
// unique (row,col) cells: ~3x3 loads instead of 64 per bin.
// ---------------------------------------------------------------------------
__global__ void pool_kernel(const float* __restrict__ xt,
                            const float* __restrict__ rois,
                            const float* __restrict__ off,
                            float* __restrict__ out) {
    int n = blockIdx.x;
    int t = threadIdx.x;   // channel

    const float* r = rois + n*5;
    int   b  = (int)r[0];
    float sw = rintf(r[1])*SS_ - 0.5f;
    float sh = rintf(r[2])*SS_ - 0.5f;
    float rw = fmaxf((rintf(r[3]) + 1.0f)*SS_ - 0.5f - sw, 0.1f);
    float rh = fmaxf((rintf(r[4]) + 1.0f)*SS_ - 0.5f - sh, 0.1f);
    float bw = rw / (float)OUT_;
    float bh = rh / (float)OUT_;

    __shared__ float s_wx[8], s_wy[8];
    __shared__ int   s_xa, s_ya, s_nx, s_ny, s_cx, s_cy;

    const int base_b = b * (H_*W_) * C_;

    for (int bin = 0; bin < NBIN; bin++) {
        int ph = bin / OUT_, pw = bin % OUT_;
        if (t == 0) {   // x side
            float txo = off ? off[n*(2*NBIN) + bin] * TRANS_STD_ : 0.0f;
            float wstart = pw*bw + sw + txo*rw;
            int xa = 1000, xb = -1000, cx = 0;
            #pragma unroll
            for (int j = 0; j < 4; j++) {
                float sx = wstart + (float)j * (bw*0.25f);
                if (sx >= -0.5f && sx <= (float)W_ - 0.5f) {
                    cx++;
                    float xc = fminf(fmaxf(sx, 0.0f), (float)(W_-1));
                    int xi0 = (int)floorf(xc);
                    int xi1 = (int)ceilf(xc);
                    xa = min(xa, xi0); xb = max(xb, xi1);
                }
            }
            int nx = (cx > 0) ? (xb - xa + 1) : 0;
            if (nx > 8) nx = 8;
            float wl[8];
            #pragma unroll
            for (int q = 0; q < 8; q++) wl[q] = 0.0f;
            #pragma unroll
            for (int j = 0; j < 4; j++) {
                float sx = wstart + (float)j * (bw*0.25f);
                if (sx >= -0.5f && sx <= (float)W_ - 0.5f) {
                    float xc = fminf(fmaxf(sx, 0.0f), (float)(W_-1));
                    float x0 = floorf(xc);
                    float dx = xc - x0;
                    int xi0 = (int)x0;
                    int xi1 = (int)ceilf(xc);
                    wl[xi0 - xa] += 1.0f - dx;
                    if (xi1 - xa < 8) wl[xi1 - xa] += dx;
                }
            }
            s_xa = xa; s_nx = nx; s_cx = cx;
            #pragma unroll
            for (int q = 0; q < 8; q++) s_wx[q] = wl[q];
        }
        if (t == 32) {  // y side (independent warp)
            float tyo = off ? off[n*(2*NBIN) + NBIN + bin] * TRANS_STD_ : 0.0f;
            float hstart = ph*bh + sh + tyo*rh;
            int ya = 1000, yb = -1000, cy = 0;
            #pragma unroll
            for (int i = 0; i < 4; i++) {
                float sy = hstart + (float)i * (bh*0.25f);
                if (sy >= -0.5f && sy <= (float)H_ - 0.5f) {
                    cy++;
                    float yc = fminf(fmaxf(sy, 0.0f), (float)(H_-1));
                    int yi0 = (int)floorf(yc);
                    int yi1 = (int)ceilf(yc);
                    ya = min(ya, yi0); yb = max(yb, yi1);
                }
            }
            int ny = (cy > 0) ? (yb - ya + 1) : 0;
            if (ny > 8) ny = 8;
            float wl[8];
            #pragma unroll
            for (int q = 0; q < 8; q++) wl[q] = 0.0f;
            #pragma unroll
            for (int i = 0; i < 4; i++) {
                float sy = hstart + (float)i * (bh*0.25f);
                if (sy >= -0.5f && sy <= (float)H_ - 0.5f) {
                    float yc = fminf(fmaxf(sy, 0.0f), (float)(H_-1));
                    float y0 = floorf(yc);
                    float dy = yc - y0;
                    int yi0 = (int)y0;
                    int yi1 = (int)ceilf(yc);
                    wl[yi0 - ya] += 1.0f - dy;
                    if (yi1 - ya < 8) wl[yi1 - ya] += dy;
                }
            }
            s_ya = ya; s_ny = ny; s_cy = cy;
            #pragma unroll
            for (int q = 0; q < 8; q++) s_wy[q] = wl[q];
        }
        __syncthreads();

        float inv = 1.0f / fmaxf((float)(s_cx * s_cy), 1.0f);
        float acc = 0.0f;
        int ny = s_ny, nx = s_nx, ya = s_ya, xa = s_xa;
        for (int iy = 0; iy < ny; iy++) {
            float wy = s_wy[iy];
            if (wy == 0.0f) continue;
            int rowoff = base_b + ((ya + iy)*W_ + xa)*C_ + t;
            for (int ix = 0; ix < nx; ix++) {
                float wv = wy * s_wx[ix];
                if (wv != 0.0f) acc += wv * xt[rowoff + ix*C_];
            }
        }
        out[n*IN_ + t*NBIN + bin] = acc * inv;
        __syncthreads();
    }
}

// ---------------------------------------------------------------------------
// 3xTF32 tensor-core GEMM, split-K.
// part[s][n][m] = sum_{k in chunk s} A[n][k] * Wm[m][k]
// CTA tile 128(n) x 128(m), BK=16, 256 threads = 8 warps of 32x64.
// Each fp32 split hi/lo tf32; 3 mma per fragment pair (hh, hl, lh).
// Smem chunk layout per row (16 k): 8 float4 chunks
//   chunk q of k8-group g = (hi_k, hi_{k+4}, lo_k, lo_{k+4}),  k = g*8+q
// physical chunk = c ^ (4*(row&1)) ^ ((row>>1)&3)  -> conflict-free frag loads
// ---------------------------------------------------------------------------
__device__ __forceinline__ uint32_t f2tf(float f) {
    uint32_t r; asm("cvt.rna.tf32.f32 %0, %1;" : "=r"(r) : "f"(f)); return r;
}
__device__ __forceinline__ void mma_tf32(float* c, uint32_t a0, uint32_t a1,
                                         uint32_t a2, uint32_t a3,
                                         uint32_t b0, uint32_t b1) {
    asm volatile(
        "mma.sync.aligned.m16n8k8.row.col.f32.tf32.tf32.f32 "
        "{%0,%1,%2,%3}, {%4,%5,%6,%7}, {%8,%9}, {%0,%1,%2,%3};"
        : "+f"(c[0]), "+f"(c[1]), "+f"(c[2]), "+f"(c[3])
        : "r"(a0), "r"(a1), "r"(a2), "r"(a3), "r"(b0), "r"(b1));
}
__device__ __forceinline__ int swz(int row, int c) {
    return c ^ (4*(row & 1)) ^ ((row >> 1) & 3);
}

__global__ __launch_bounds__(256) void gemm_tc(
    const float* __restrict__ A, const float* __restrict__ Wm,
    float* __restrict__ part, int M, int K, int Kc) {
    __shared__ float4 sA[128][8];   // 16 KB
    __shared__ float4 sW[128][8];   // 16 KB

    int tid = threadIdx.x;
    int m0 = blockIdx.x * 128;
    int n0 = blockIdx.y * 128;
    int s  = blockIdx.z;
    int k0 = s * Kc;
    int ntile = Kc / 16;

    int w = tid >> 5, lane = tid & 31;
    int wr = w >> 1, wc = w & 1;          // 4 row-groups x 2 col-groups

    float acc[2][8][4];
    #pragma unroll
    for (int i = 0; i < 2; i++)
        #pragma unroll
        for (int j = 0; j < 8; j++)
            #pragma unroll
            for (int q = 0; q < 4; q++) acc[i][j][q] = 0.0f;

    // Load tasks: every thread loads one A row-slab and one W row-slab.
    int lrow = tid >> 1;        // 0..127
    int lk8  = tid & 1;         // which k8 of the 16-k tile
    const float* gA = A  + (size_t)(n0 + lrow)*K + k0 + lk8*8;
    const float* gW = Wm + (size_t)(m0 + lrow)*K + k0 + lk8*8;

    float4 ra0, ra1, rw0, rw1;
    ra0 = *(const float4*)(gA);     ra1 = *(const float4*)(gA + 4);
    rw0 = *(const float4*)(gW);     rw1 = *(const float4*)(gW + 4);

    for (int t = 0; t < ntile; t++) {
        __syncthreads();            // previous tile's reads complete
        {   // pack + store current prefetch into smem
            const float* a0 = (const float*)&ra0;
            const float* a1 = (const float*)&ra1;
            const float* w0 = (const float*)&rw0;
            const float* w1 = (const float*)&rw1;
            #pragma unroll
            for (int q = 0; q < 4; q++) {
                uint32_t h0 = f2tf(a0[q]);
                uint32_t h1 = f2tf(a1[q]);
                float4 v;
                v.x = __uint_as_float(h0);
                v.y = __uint_as_float(h1);
                v.z = __uint_as_float(f2tf(a0[q] - __uint_as_float(h0)));
                v.w = __uint_as_float(f2tf(a1[q] - __uint_as_float(h1)));
                sA[lrow][swz(lrow, lk8*4 + q)] = v;
                h0 = f2tf(w0[q]);
                h1 = f2tf(w1[q]);
                v.x = __uint_as_float(h0);
                v.y = __uint_as_float(h1);
                v.z = __uint_as_float(f2tf(w0[q] - __uint_as_float(h0)));
                v.w = __uint_as_float(f2tf(w1[q] - __uint_as_float(h1)));
                sW[lrow][swz(lrow, lk8*4 + q)] = v;
            }
        }
        __syncthreads();            // smem tile ready
        if (t + 1 < ntile) {        // prefetch next tile (in flight during mma)
            ra0 = *(const float4*)(gA + (t+1)*16);
            ra1 = *(const float4*)(gA + (t+1)*16 + 4);
            rw0 = *(const float4*)(gW + (t+1)*16);
            rw1 = *(const float4*)(gW + (t+1)*16 + 4);
        }

        #pragma unroll
        for (int k8 = 0; k8 < 2; k8++) {
            int cbase = k8*4 + (lane & 3);
            // A fragments: 2 m16 tiles
            uint32_t ah[2][4], al[2][4];
            #pragma unroll
            for (int i = 0; i < 2; i++) {
                int rl = wr*32 + i*16 + (lane >> 2);
                int rh = rl + 8;
                float4 fl = sA[rl][swz(rl, cbase)];
                float4 fh = sA[rh][swz(rh, cbase)];
                ah[i][0] = __float_as_uint(fl.x); // a0 hi  (row, k)
                ah[i][2] = __float_as_uint(fl.y); // a2 hi  (row, k+4)
                al[i][0] = __float_as_uint(fl.z);
                al[i][2] = __float_as_uint(fl.w);
                ah[i][1] = __float_as_uint(fh.x); // a1 hi  (row+8, k)
                ah[i][3] = __float_as_uint(fh.y); // a3 hi  (row+8, k+4)
                al[i][1] = __float_as_uint(fh.z);
                al[i][3] = __float_as_uint(fh.w);
            }
            #pragma unroll
            for (int j = 0; j < 8; j++) {
                int m = wc*64 + j*8 + (lane >> 2);
                float4 fb = sW[m][swz(m, cbase)];
                uint32_t bh0 = __float_as_uint(fb.x);
                uint32_t bh1 = __float_as_uint(fb.y);
                uint32_t bl0 = __float_as_uint(fb.z);
                uint32_t bl1 = __float_as_uint(fb.w);
                #pragma unroll
                for (int i = 0; i < 2; i++) {
                    mma_tf32(acc[i][j], ah[i][0],ah[i][1],ah[i][2],ah[i][3], bh0, bh1);
                    mma_tf32(acc[i][j], ah[i][0],ah[i][1],ah[i][2],ah[i][3], bl0, bl1);
                    mma_tf32(acc[i][j], al[i][0],al[i][1],al[i][2],al[i][3], bh0, bh1);
                }
            }
        }
    }

    // Epilogue -> partials
    float* p = part + (size_t)s * N_ * M;
    #pragma unroll
    for (int i = 0; i < 2; i++) {
        int r0 = n0 + wr*32 + i*16 + (lane >> 2);
        #pragma unroll
        for (int j = 0; j < 8; j++) {
            int col = m0 + wc*64 + j*8 + (lane & 3)*2;
            *(float2*)(p + (size_t)r0*M + col)     = make_float2(acc[i][j][0], acc[i][j][1]);
            *(float2*)(p + (size_t)(r0+8)*M + col) = make_float2(acc[i][j][2], acc[i][j][3]);
        }
    }
}

// ---------------------------------------------------------------------------
// Reduce split-K partials + bias (+ optional relu), float4
// ---------------------------------------------------------------------------
__global__ void reduce_kernel(const float4* __restrict__ part,
                              const float* __restrict__ bias,
                              float4* __restrict__ C, int M4, int S, int relu) {
    int idx = blockIdx.x * 256 + threadIdx.x;   // over N_*M/4
    int col4 = idx % M4;
    const float4* bp = (const float4*)bias;
    float4 acc = bp[col4];
    for (int s = 0; s < S; s++) {
        float4 v = part[(size_t)s*N_*M4 + idx];
        acc.x += v.x; acc.y += v.y; acc.z += v.z; acc.w += v.w;
    }
    if (relu) {
        acc.x = fmaxf(acc.x, 0.0f); acc.y = fmaxf(acc.y, 0.0f);
        acc.z = fmaxf(acc.z, 0.0f); acc.w = fmaxf(acc.w, 0.0f);
    }
    C[idx] = acc;
}

// ---------------------------------------------------------------------------
// off3: out[n][o] = h[n] . w3[o] + b3[o]  (98 outputs, K=1024)
// ---------------------------------------------------------------------------
__global__ void off3_kernel(const float* __restrict__ h,
                            const float* __restrict__ w3,
                            const float* __restrict__ b3,
                            float* __restrict__ out) {
    int n = blockIdx.x;
    int tid = threadIdx.x;
    __shared__ float sh[DFC_];
    ((float4*)sh)[tid] = ((const float4*)(h + n*DFC_))[tid];
    __syncthreads();
    int warp = tid >> 5, lane = tid & 31;
    for (int o = warp; o < 2*NBIN; o += 8) {
        const float4* w = (const float4*)(w3 + o*DFC_);
        float acc = 0.0f;
        #pragma unroll
        for (int i = lane; i < DFC_/4; i += 32) {
            float4 wv = w[i];
            float4 av = ((const float4*)sh)[i];
            acc += wv.x*av.x + wv.y*av.y + wv.z*av.z + wv.w*av.w;
        }
        #pragma unroll
        for (int d = 16; d > 0; d >>= 1) acc += __shfl_down_sync(0xffffffffu, acc, d);
        if (lane == 0) out[n*(2*NBIN) + o] = acc + b3[o];
    }
}

// ---------------------------------------------------------------------------
// box: out[n][w] = f2[n] . box_w[w] + box_b[w]
// ---------------------------------------------------------------------------
__global__ void box_kernel(const float* __restrict__ f2,
                           const float* __restrict__ bw,
                           const float* __restrict__ bb,
                           float* __restrict__ out) {
    int n = blockIdx.x;
    int w = threadIdx.x >> 5;
    int lane = threadIdx.x & 31;
    float acc = 0.0f;
    for (int k = lane; k < FCC_; k += 32) acc += f2[n*FCC_ + k]*bw[w*FCC_ + k];
    #pragma unroll
    for (int o = 16; o > 0; o >>= 1) acc += __shfl_down_sync(0xffffffffu, acc, o);
    if (lane == 0) out[n*4 + w] = acc + bb[w];
}

// ---------------------------------------------------------------------------
extern "C" void kernel_launch(void* const* d_in, const int* in_sizes, int n_in,
                              void* d_out, int out_size) {
    const float* x      = (const float*)d_in[0];
    const float* rois   = (const float*)d_in[1];
    const float* off_w1 = (const float*)d_in[2];
    const float* off_b1 = (const float*)d_in[3];
    const float* off_w2 = (const float*)d_in[4];
    const float* off_b2 = (const float*)d_in[5];
    const float* off_w3 = (const float*)d_in[6];
    const float* off_b3 = (const float*)d_in[7];
    const float* fc1_w  = (const float*)d_in[8];
    const float* fc1_b  = (const float*)d_in[9];
    const float* fc2_w  = (const float*)d_in[10];
    const float* fc2_b  = (const float*)d_in[11];
    const float* box_w  = (const float*)d_in[12];
    const float* box_b  = (const float*)d_in[13];
    float* out = (float*)d_out;

    float *xt, *p0, *h1, *h2, *offb, *p1, *f1, *f2, *part;
    cudaGetSymbolAddress((void**)&xt,   g_xt);
    cudaGetSymbolAddress((void**)&p0,   g_p0);
    cudaGetSymbolAddress((void**)&h1,   g_h1);
    cudaGetSymbolAddress((void**)&h2,   g_h2);
    cudaGetSymbolAddress((void**)&offb, g_off);
    cudaGetSymbolAddress((void**)&p1,   g_p1);
    cudaGetSymbolAddress((void**)&f1,   g_f1);
    cudaGetSymbolAddress((void**)&f2,   g_f2);
    cudaGetSymbolAddress((void**)&part, g_part);

    // 1. x -> xt
    {
        dim3 grid((H_*W_ + 31)/32, (C_ + 31)/32, B_);
        dim3 block(32, 8);
        transpose_kernel<<<grid, block>>>(x, xt);
    }
    // 2. pool with zero offsets -> p0
    pool_kernel<<<N_, 256>>>(xt, rois, nullptr, p0);

    // 3. h1 = relu(p0 @ off_w1^T + off_b1)  [256x1024, K=12544], S=8
    gemm_tc<<<dim3(DFC_/128, 2, 8), 256>>>(p0, off_w1, part, DFC_, IN_, IN_/8);
    reduce_kernel<<<(N_*DFC_/4)/256, 256>>>((const float4*)part, off_b1, (float4*)h1, DFC_/4, 8, 1);

    // 4. h2 = relu(h1 @ off_w2^T + off_b2)  [256x1024, K=1024], S=8
    gemm_tc<<<dim3(DFC_/128, 2, 8), 256>>>(h1, off_w2, part, DFC_, DFC_, DFC_/8);
    reduce_kernel<<<(N_*DFC_/4)/256, 256>>>((const float4*)part, off_b2, (float4*)h2, DFC_/4, 8, 1);

    // 5. off = h2 @ off_w3^T + off_b3       [256x98]
    off3_kernel<<<N_, 256>>>(h2, off_w3, off_b3, offb);

    // 6. pool with learned offsets -> p1
    pool_kernel<<<N_, 256>>>(xt, rois, offb, p1);

    // 7. f1 = relu(p1 @ fc1_w^T + fc1_b)    [256x512, K=12544], S=16
    gemm_tc<<<dim3(FCC_/128, 2, 16), 256>>>(p1, fc1_w, part, FCC_, IN_, IN_/16);
    reduce_kernel<<<(N_*FCC_/4)/256, 256>>>((const float4*)part, fc1_b, (float4*)f1, FCC_/4, 16, 1);

    // 8. f2 = relu(f1 @ fc2_w^T + fc2_b)    [256x512, K=512], S=8
    gemm_tc<<<dim3(FCC_/128, 2, 8), 256>>>(f1, fc2_w, part, FCC_, FCC_, FCC_/8);
    reduce_kernel<<<(N_*FCC_/4)/256, 256>>>((const float4*)part, fc2_b, (float4*)f2, FCC_/4, 8, 1);

    // 9. out = f2 @ box_w^T + box_b         [256x4]
    box_kernel<<<N_, 128>>>(f2, box_w, box_b, out);
}

// round 11
// speedup vs baseline: 1.8854x; 1.8854x over previous
#include <cuda_runtime.h>
#include <cuda_bf16.h>
#include <cstdint>

// Problem constants
#define B_ 8
#define C_ 256
#define H_ 25
#define W_ 25
#define N_ 256
#define OUT_ 7
#define NBIN 49
#define IN_ 12544   // C*7*7
#define DFC_ 1024
#define FCC_ 512
#define SS_ (25.0f/255.0f)
#define TRANS_STD_ 0.1f

// fp32 scratch
__device__ float g_xt[B_*H_*W_*C_];
__device__ float g_p0[N_*IN_];
__device__ float g_h1[N_*DFC_];
__device__ float g_h2[N_*DFC_];
__device__ float g_off[N_*2*NBIN];
__device__ float g_p1[N_*IN_];
__device__ float g_f1[N_*FCC_];
__device__ float g_f2[N_*FCC_];
__device__ float g_part[3670016];      // split-K partials (max 14*256*1024 == 28*256*512)

// bf16 hi/lo fragment-ordered buffers (uint4 = 4 regs x 2 bf16 = 8 elements)
__device__ uint4 g_w1hi[1605632], g_w1lo[1605632];   // off_w1 1024x12544
__device__ uint4 g_w2hi[131072],  g_w2lo[131072];    // off_w2 1024x1024
__device__ uint4 g_q1hi[802816],  g_q1lo[802816];    // fc1_w  512x12544
__device__ uint4 g_q2hi[32768],   g_q2lo[32768];     // fc2_w  512x512
__device__ uint4 g_ahi[401408],   g_alo[401408];     // activations (256x12544 / 8)

// ---------------------------------------------------------------------------
// Transpose x (B,C,H,W) -> xt (B,H*W,C)
// ---------------------------------------------------------------------------
__global__ void transpose_kernel(const float* __restrict__ x, float* __restrict__ xt) {
    __shared__ float tile[32][33];
    int b  = blockIdx.z;
    int s0 = blockIdx.x * 32;
    int c0 = blockIdx.y * 32;
    int tx = threadIdx.x, ty = threadIdx.y;
    const int HW = H_*W_;
    #pragma unroll
    for (int i = ty; i < 32; i += 8) {
        int c = c0 + i, s = s0 + tx;
        if (c < C_ && s < HW) tile[i][tx] = x[(b*C_ + c)*HW + s];
    }
    __syncthreads();
    #pragma unroll
    for (int i = ty; i < 32; i += 8) {
        int s = s0 + i, c = c0 + tx;
        if (s < HW && c < C_) xt[(b*HW + s)*C_ + c] = tile[tx][i];
    }
}

// ---------------------------------------------------------------------------
// Deformable ROI pool, factorized (passed in R4)
// ---------------------------------------------------------------------------
__global__ void pool_kernel(const float* __restrict__ xt,
                            const float* __restrict__ rois,
                            const float* __restrict__ off,
                            float* __restrict__ out) {
    int n = blockIdx.x;
    int t = threadIdx.x;

    const float* r = rois + n*5;
    int   b  = (int)r[0];
    float sw = rintf(r[1])*SS_ - 0.5f;
    float sh = rintf(r[2])*SS_ - 0.5f;
    float rw = fmaxf((rintf(r[3]) + 1.0f)*SS_ - 0.5f - sw, 0.1f);
    float rh = fmaxf((rintf(r[4]) + 1.0f)*SS_ - 0.5f - sh, 0.1f);
    float bw = rw / (float)OUT_;
    float bh = rh / (float)OUT_;

    __shared__ float s_wx[8], s_wy[8];
    __shared__ int   s_xa, s_ya, s_nx, s_ny, s_cx, s_cy;

    const int base_b = b * (H_*W_) * C_;

    for (int bin = 0; bin < NBIN; bin++) {
        int ph = bin / OUT_, pw = bin % OUT_;
        if (t == 0) {
            float txo = off ? off[n*(2*NBIN) + bin] * TRANS_STD_ : 0.0f;
            float wstart = pw*bw + sw + txo*rw;
            int xa = 1000, xb = -1000, cx = 0;
            #pragma unroll
            for (int j = 0; j < 4; j++) {
                float sx = wstart + (float)j * (bw*0.25f);
                if (sx >= -0.5f && sx <= (float)W_ - 0.5f) {
                    cx++;
                    float xc = fminf(fmaxf(sx, 0.0f), (float)(W_-1));
                    int xi0 = (int)floorf(xc);
                    int xi1 = (int)ceilf(xc);
                    xa = min(xa, xi0); xb = max(xb, xi1);
                }
            }
            int nx = (cx > 0) ? (xb - xa + 1) : 0;
            if (nx > 8) nx = 8;
            float wl[8];
            #pragma unroll
            for (int q = 0; q < 8; q++) wl[q] = 0.0f;
            #pragma unroll
            for (int j = 0; j < 4; j++) {
                float sx = wstart + (float)j * (bw*0.25f);
                if (sx >= -0.5f && sx <= (float)W_ - 0.5f) {
                    float xc = fminf(fmaxf(sx, 0.0f), (float)(W_-1));
                    float x0 = floorf(xc);
                    float dx = xc - x0;
                    int xi0 = (int)x0;
                    int xi1 = (int)ceilf(xc);
                    wl[xi0 - xa] += 1.0f - dx;
                    if (xi1 - xa < 8) wl[xi1 - xa] += dx;
                }
            }
            s_xa = xa; s_nx = nx; s_cx = cx;
            #pragma unroll
            for (int q = 0; q < 8; q++) s_wx[q] = wl[q];
        }
        if (t == 32) {
            float tyo = off ? off[n*(2*NBIN) + NBIN + bin] * TRANS_STD_ : 0.0f;
            float hstart = ph*bh + sh + tyo*rh;
            int ya = 1000, yb = -1000, cy = 0;
            #pragma unroll
            for (int i = 0; i < 4; i++) {
                float sy = hstart + (float)i * (bh*0.25f);
                if (sy >= -0.5f && sy <= (float)H_ - 0.5f) {
                    cy++;
                    float yc = fminf(fmaxf(sy, 0.0f), (float)(H_-1));
                    int yi0 = (int)floorf(yc);
                    int yi1 = (int)ceilf(yc);
                    ya = min(ya, yi0); yb = max(yb, yi1);
                }
            }
            int ny = (cy > 0) ? (yb - ya + 1) : 0;
            if (ny > 8) ny = 8;
            float wl[8];
            #pragma unroll
            for (int q = 0; q < 8; q++) wl[q] = 0.0f;
            #pragma unroll
            for (int i = 0; i < 4; i++) {
                float sy = hstart + (float)i * (bh*0.25f);
                if (sy >= -0.5f && sy <= (float)H_ - 0.5f) {
                    float yc = fminf(fmaxf(sy, 0.0f), (float)(H_-1));
                    float y0 = floorf(yc);
                    float dy = yc - y0;
                    int yi0 = (int)y0;
                    int yi1 = (int)ceilf(yc);
                    wl[yi0 - ya] += 1.0f - dy;
                    if (yi1 - ya < 8) wl[yi1 - ya] += dy;
                }
            }
            s_ya = ya; s_ny = ny; s_cy = cy;
            #pragma unroll
            for (int q = 0; q < 8; q++) s_wy[q] = wl[q];
        }
        __syncthreads();

        float inv = 1.0f / fmaxf((float)(s_cx * s_cy), 1.0f);
        float acc = 0.0f;
        int ny = s_ny, nx = s_nx, ya = s_ya, xa = s_xa;
        for (int iy = 0; iy < ny; iy++) {
            float wy = s_wy[iy];
            if (wy == 0.0f) continue;
            int rowoff = base_b + ((ya + iy)*W_ + xa)*C_ + t;
            for (int ix = 0; ix < nx; ix++) {
                float wv = wy * s_wx[ix];
                if (wv != 0.0f) acc += wv * xt[rowoff + ix*C_];
            }
        }
        out[n*IN_ + t*NBIN + bin] = acc * inv;
        __syncthreads();
    }
}

// ---------------------------------------------------------------------------
// fp32 -> bf16 hi/lo pack: reg = {lo bits: even elem, hi bits: odd elem}
// ---------------------------------------------------------------------------
__device__ __forceinline__ void packpair(float e, float o, uint32_t& h, uint32_t& l) {
    asm("cvt.rn.bf16x2.f32 %0, %1, %2;" : "=r"(h) : "f"(o), "f"(e));
    float re = e - __uint_as_float(h << 16);
    float ro = o - __uint_as_float(h & 0xffff0000u);
    asm("cvt.rn.bf16x2.f32 %0, %1, %2;" : "=r"(l) : "f"(ro), "f"(re));
}

// ---------------------------------------------------------------------------
// Weight -> fragment-ordered bf16 hi/lo.
// uint4 id = ((mb*KT + kt)*8 + wt)*32 + lane.
// ---------------------------------------------------------------------------
__global__ void conv_frag_w(const float* __restrict__ Wm, uint4* __restrict__ hi,
                            uint4* __restrict__ lo, int K, int total) {
    int tid = blockIdx.x * 256 + threadIdx.x;
    if (tid >= total) return;
    int lane = tid & 31;
    int rest = tid >> 5;
    int wt = rest & 7; rest >>= 3;
    int KT = K >> 4;
    int kt = rest % KT;
    int mb = rest / KT;
    int m0 = mb*128 + wt*16 + (lane >> 2);
    int k0 = kt*16 + (lane & 3)*2;
    uint4 h, l;
    const float* p00 = Wm + (size_t)m0*K + k0;
    const float* p10 = Wm + (size_t)(m0+8)*K + k0;
    packpair(p00[0], p00[1], h.x, l.x);       // frag0.b0
    packpair(p00[8], p00[9], h.y, l.y);       // frag0.b1
    packpair(p10[0], p10[1], h.z, l.z);       // frag1.b0
    packpair(p10[8], p10[9], h.w, l.w);       // frag1.b1
    hi[tid] = h; lo[tid] = l;
}

// ---------------------------------------------------------------------------
// Activation -> fragment-ordered bf16 hi/lo (A operand).
// uint4 id = ((nb*KT + kt)*8 + at)*32 + lane.
// ---------------------------------------------------------------------------
__global__ void conv_frag_a(const float* __restrict__ A, uint4* __restrict__ hi,
                            uint4* __restrict__ lo, int K, int total) {
    int tid = blockIdx.x * 256 + threadIdx.x;
    if (tid >= total) return;
    int lane = tid & 31;
    int rest = tid >> 5;
    int at = rest & 7; rest >>= 3;
    int KT = K >> 4;
    int kt = rest % KT;
    int nb = rest / KT;
    int m0 = nb*128 + at*16 + (lane >> 2);
    int k0 = kt*16 + (lane & 3)*2;
    uint4 h, l;
    const float* p00 = A + (size_t)m0*K + k0;
    const float* p10 = A + (size_t)(m0+8)*K + k0;
    packpair(p00[0], p00[1], h.x, l.x);       // a0
    packpair(p10[0], p10[1], h.y, l.y);       // a1
    packpair(p00[8], p00[9], h.z, l.z);       // a2
    packpair(p10[8], p10[9], h.w, l.w);       // a3
    hi[tid] = h; lo[tid] = l;
}

// ---------------------------------------------------------------------------
// bf16 3-term mma.sync GEMM, split-K, no smem.
// CTA 128(n) x 128(m), 8 warps (wr 0-3 x wc 0-1), warp tile 32x64.
// ---------------------------------------------------------------------------
__device__ __forceinline__ void mma_bf16(float* c, const uint4& a,
                                         uint32_t b0, uint32_t b1) {
    asm volatile(
        "mma.sync.aligned.m16n8k16.row.col.f32.bf16.bf16.f32 "
        "{%0,%1,%2,%3}, {%4,%5,%6,%7}, {%8,%9}, {%0,%1,%2,%3};"
        : "+f"(c[0]), "+f"(c[1]), "+f"(c[2]), "+f"(c[3])
        : "r"(a.x), "r"(a.y), "r"(a.z), "r"(a.w), "r"(b0), "r"(b1));
}

__global__ __launch_bounds__(256, 2) void gemm_bf16(
    const uint4* __restrict__ Ahi, const uint4* __restrict__ Alo,
    const uint4* __restrict__ Whi, const uint4* __restrict__ Wlo,
    float* __restrict__ part, int M, int KT, int Kc16) {
    int tid = threadIdx.x, wid = tid >> 5, lane = tid & 31;
    int wr = wid >> 1, wc = wid & 1;
    int mb = blockIdx.x, nb = blockIdx.y, s = blockIdx.z;

    float acc[2][8][4];
    #pragma unroll
    for (int i = 0; i < 2; i++)
        #pragma unroll
        for (int j = 0; j < 8; j++)
            #pragma unroll
            for (int q = 0; q < 4; q++) acc[i][j][q] = 0.0f;

    int kt0 = s * Kc16;
    int at0 = wr*2;

    for (int t = 0; t < Kc16; t++) {
        int kt = kt0 + t;
        int baseA = ((nb*KT + kt)*8)*32 + lane;
        uint4 ah0 = Ahi[baseA + at0*32];
        uint4 ah1 = Ahi[baseA + (at0+1)*32];
        uint4 al0 = Alo[baseA + at0*32];
        uint4 al1 = Alo[baseA + (at0+1)*32];
        int baseW = ((mb*KT + kt)*8)*32 + lane + wc*4*32;
        #pragma unroll
        for (int wt = 0; wt < 4; wt++) {
            uint4 wh = Whi[baseW + wt*32];
            uint4 wl = Wlo[baseW + wt*32];
            int nf = wt*2;
            mma_bf16(acc[0][nf],   ah0, wh.x, wh.y);
            mma_bf16(acc[0][nf+1], ah0, wh.z, wh.w);
            mma_bf16(acc[1][nf],   ah1, wh.x, wh.y);
            mma_bf16(acc[1][nf+1], ah1, wh.z, wh.w);
            mma_bf16(acc[0][nf],   ah0, wl.x, wl.y);
            mma_bf16(acc[0][nf+1], ah0, wl.z, wl.w);
            mma_bf16(acc[1][nf],   ah1, wl.x, wl.y);
            mma_bf16(acc[1][nf+1], ah1, wl.z, wl.w);
            mma_bf16(acc[0][nf],   al0, wh.x, wh.y);
            mma_bf16(acc[0][nf+1], al0, wh.z, wh.w);
            mma_bf16(acc[1][nf],   al1, wh.x, wh.y);
            mma_bf16(acc[1][nf+1], al1, wh.z, wh.w);
        }
    }

    float* p = part + (size_t)s * N_ * M;
    #pragma unroll
    for (int i = 0; i < 2; i++) {
        int row = nb*128 + wr*32 + i*16 + (lane >> 2);
        #pragma unroll
        for (int nf = 0; nf < 8; nf++) {
            int col = mb*128 + wc*64 + nf*8 + (lane & 3)*2;
            *(float2*)(p + (size_t)row*M + col)     = make_float2(acc[i][nf][0], acc[i][nf][1]);
            *(float2*)(p + (size_t)(row+8)*M + col) = make_float2(acc[i][nf][2], acc[i][nf][3]);
        }
    }
}

// ---------------------------------------------------------------------------
// Reduce split-K partials + bias (+ optional relu), float4
// ---------------------------------------------------------------------------
__global__ void reduce_kernel(const float4* __restrict__ part,
                              const float* __restrict__ bias,
                              float4* __restrict__ C, int M4, int S, int relu) {
    int idx = blockIdx.x * 256 + threadIdx.x;
    int col4 = idx % M4;
    const float4* bp = (const float4*)bias;
    float4 acc = bp[col4];
    for (int s = 0; s < S; s++) {
        float4 v = part[(size_t)s*N_*M4 + idx];
        acc.x += v.x; acc.y += v.y; acc.z += v.z; acc.w += v.w;
    }
    if (relu) {
        acc.x = fmaxf(acc.x, 0.0f); acc.y = fmaxf(acc.y, 0.0f);
        acc.z = fmaxf(acc.z, 0.0f); acc.w = fmaxf(acc.w, 0.0f);
    }
    C[idx] = acc;
}

// ---------------------------------------------------------------------------
// off3: out[n][o] = h[n] . w3[o] + b3[o]  (98 outputs, K=1024)
// ---------------------------------------------------------------------------
__global__ void off3_kernel(const float* __restrict__ h,
                            const float* __restrict__ w3,
                            const float* __restrict__ b3,
                            float* __restrict__ out) {
    int n = blockIdx.x;
    int tid = threadIdx.x;
    __shared__ float sh[DFC_];
    ((float4*)sh)[tid] = ((const float4*)(h + n*DFC_))[tid];
    __syncthreads();
    int warp = tid >> 5, lane = tid & 31;
    for (int o = warp; o < 2*NBIN; o += 8) {
        const float4* w = (const float4*)(w3 + o*DFC_);
        float acc = 0.0f;
        #pragma unroll
        for (int i = lane; i < DFC_/4; i += 32) {
            float4 wv = w[i];
            float4 av = ((const float4*)sh)[i];
            acc += wv.x*av.x + wv.y*av.y + wv.z*av.z + wv.w*av.w;
        }
        #pragma unroll
        for (int d = 16; d > 0; d >>= 1) acc += __shfl_down_sync(0xffffffffu, acc, d);
        if (lane == 0) out[n*(2*NBIN) + o] = acc + b3[o];
    }
}

// ---------------------------------------------------------------------------
// box head
// ---------------------------------------------------------------------------
__global__ void box_kernel(const float* __restrict__ f2,
                           const float* __restrict__ bw,
                           const float* __restrict__ bb,
                           float* __restrict__ out) {
    int n = blockIdx.x;
    int w = threadIdx.x >> 5;
    int lane = threadIdx.x & 31;
    float acc = 0.0f;
    for (int k = lane; k < FCC_; k += 32) acc += f2[n*FCC_ + k]*bw[w*FCC_ + k];
    #pragma unroll
    for (int o = 16; o > 0; o >>= 1) acc += __shfl_down_sync(0xffffffffu, acc, o);
    if (lane == 0) out[n*4 + w] = acc + bb[w];
}

// ---------------------------------------------------------------------------
extern "C" void kernel_launch(void* const* d_in, const int* in_sizes, int n_in,
                              void* d_out, int out_size) {
    const float* x      = (const float*)d_in[0];
    const float* rois   = (const float*)d_in[1];
    const float* off_w1 = (const float*)d_in[2];
    const float* off_b1 = (const float*)d_in[3];
    const float* off_w2 = (const float*)d_in[4];
    const float* off_b2 = (const float*)d_in[5];
    const float* off_w3 = (const float*)d_in[6];
    const float* off_b3 = (const float*)d_in[7];
    const float* fc1_w  = (const float*)d_in[8];
    const float* fc1_b  = (const float*)d_in[9];
    const float* fc2_w  = (const float*)d_in[10];
    const float* fc2_b  = (const float*)d_in[11];
    const float* box_w  = (const float*)d_in[12];
    const float* box_b  = (const float*)d_in[13];
    float* out = (float*)d_out;

    float *xt, *p0, *h1, *h2, *offb, *p1, *f1, *f2, *part;
    uint4 *w1hi, *w1lo, *w2hi, *w2lo, *q1hi, *q1lo, *q2hi, *q2lo, *ahi, *alo;
    cudaGetSymbolAddress((void**)&xt,   g_xt);
    cudaGetSymbolAddress((void**)&p0,   g_p0);
    cudaGetSymbolAddress((void**)&h1,   g_h1);
    cudaGetSymbolAddress((void**)&h2,   g_h2);
    cudaGetSymbolAddress((void**)&offb, g_off);
    cudaGetSymbolAddress((void**)&p1,   g_p1);
    cudaGetSymbolAddress((void**)&f1,   g_f1);
    cudaGetSymbolAddress((void**)&f2,   g_f2);
    cudaGetSymbolAddress((void**)&part, g_part);
    cudaGetSymbolAddress((void**)&w1hi, g_w1hi);
    cudaGetSymbolAddress((void**)&w1lo, g_w1lo);
    cudaGetSymbolAddress((void**)&w2hi, g_w2hi);
    cudaGetSymbolAddress((void**)&w2lo, g_w2lo);
    cudaGetSymbolAddress((void**)&q1hi, g_q1hi);
    cudaGetSymbolAddress((void**)&q1lo, g_q1lo);
    cudaGetSymbolAddress((void**)&q2hi, g_q2hi);
    cudaGetSymbolAddress((void**)&q2lo, g_q2lo);
    cudaGetSymbolAddress((void**)&ahi,  g_ahi);
    cudaGetSymbolAddress((void**)&alo,  g_alo);

    // Weight conversions (independent of data path; issued first)
    conv_frag_w<<<6272, 256>>>(off_w1, w1hi, w1lo, IN_,  1605632);
    conv_frag_w<<<512,  256>>>(off_w2, w2hi, w2lo, DFC_, 131072);
    conv_frag_w<<<3136, 256>>>(fc1_w,  q1hi, q1lo, IN_,  802816);
    conv_frag_w<<<128,  256>>>(fc2_w,  q2hi, q2lo, FCC_, 32768);

    // 1. x -> xt
    {
        dim3 grid((H_*W_ + 31)/32, (C_ + 31)/32, B_);
        dim3 block(32, 8);
        transpose_kernel<<<grid, block>>>(x, xt);
    }
    // 2. pool (zero offsets) -> p0, convert
    pool_kernel<<<N_, 256>>>(xt, rois, nullptr, p0);
    conv_frag_a<<<1568, 256>>>(p0, ahi, alo, IN_, 401408);

    // 3. h1 = relu(p0 @ off_w1^T + b1)  [256x1024, K=12544], S=14 (Kc16=56)
    gemm_bf16<<<dim3(8, 2, 14), 256>>>(ahi, alo, w1hi, w1lo, part, DFC_, 784, 56);
    reduce_kernel<<<(N_*DFC_/4)/256, 256>>>((const float4*)part, off_b1, (float4*)h1, DFC_/4, 14, 1);

    // 4. h2 = relu(h1 @ off_w2^T + b2)  [256x1024, K=1024], S=8 (Kc16=8)
    conv_frag_a<<<128, 256>>>(h1, ahi, alo, DFC_, 32768);
    gemm_bf16<<<dim3(8, 2, 8), 256>>>(ahi, alo, w2hi, w2lo, part, DFC_, 64, 8);
    reduce_kernel<<<(N_*DFC_/4)/256, 256>>>((const float4*)part, off_b2, (float4*)h2, DFC_/4, 8, 1);

    // 5. off = h2 @ off_w3^T + b3       [256x98]
    off3_kernel<<<N_, 256>>>(h2, off_w3, off_b3, offb);

    // 6. pool (learned offsets) -> p1, convert
    pool_kernel<<<N_, 256>>>(xt, rois, offb, p1);
    conv_frag_a<<<1568, 256>>>(p1, ahi, alo, IN_, 401408);

    // 7. f1 = relu(p1 @ fc1_w^T + b)    [256x512, K=12544], S=28 (Kc16=28)
    gemm_bf16<<<dim3(4, 2, 28), 256>>>(ahi, alo, q1hi, q1lo, part, FCC_, 784, 28);
    reduce_kernel<<<(N_*FCC_/4)/256, 256>>>((const float4*)part, fc1_b, (float4*)f1, FCC_/4, 28, 1);

    // 8. f2 = relu(f1 @ fc2_w^T + b)    [256x512, K=512], S=16 (Kc16=2)
    conv_frag_a<<<64, 256>>>(f1, ahi, alo, FCC_, 16384);
    gemm_bf16<<<dim3(4, 2, 16), 256>>>(ahi, alo, q2hi, q2lo, part, FCC_, 32, 2);
    reduce_kernel<<<(N_*FCC_/4)/256, 256>>>((const float4*)part, fc2_b, (float4*)f2, FCC_/4, 16, 1);

    // 9. out = f2 @ box_w^T + box_b     [256x4]
    box_kernel<<<N_, 128>>>(f2, box_w, box_b, out);
}

// round 13
// speedup vs baseline: 2.6952x; 1.4295x over previous
#include <cuda_runtime.h>
#include <cuda_bf16.h>
#include <cstdint>

// Problem constants
#define B_ 8
#define C_ 256
#define H_ 25
#define W_ 25
#define N_ 256
#define OUT_ 7
#define NBIN 49
#define IN_ 12544   // C*7*7
#define DFC_ 1024
#define FCC_ 512
#define SS_ (25.0f/255.0f)
#define TRANS_STD_ 0.1f

// fp32 scratch
__device__ float g_xt[B_*H_*W_*C_];
__device__ float g_p0[N_*IN_];
__device__ float g_h1[N_*DFC_];
__device__ float g_h2[N_*DFC_];
__device__ float g_off[N_*2*NBIN];
__device__ float g_p1[N_*IN_];
__device__ float g_f1[N_*FCC_];
__device__ float g_f2[N_*FCC_];
__device__ float g_part[3670016];      // split-K partials (max 14*256*1024 == 28*256*512)

// bf16 hi/lo fragment-ordered buffers (uint4 = 4 regs x 2 bf16 = 8 elements)
__device__ uint4 g_w1hi[1605632], g_w1lo[1605632];   // off_w1 1024x12544
__device__ uint4 g_w2hi[131072],  g_w2lo[131072];    // off_w2 1024x1024
__device__ uint4 g_q1hi[802816],  g_q1lo[802816];    // fc1_w  512x12544
__device__ uint4 g_q2hi[32768],   g_q2lo[32768];     // fc2_w  512x512
__device__ uint4 g_ahi[401408],   g_alo[401408];     // activations (256x12544 / 8)

// ---------------------------------------------------------------------------
// Transpose x (B,C,H,W) -> xt (B,H*W,C)
// ---------------------------------------------------------------------------
__global__ void transpose_kernel(const float* __restrict__ x, float* __restrict__ xt) {
    __shared__ float tile[32][33];
    int b  = blockIdx.z;
    int s0 = blockIdx.x * 32;
    int c0 = blockIdx.y * 32;
    int tx = threadIdx.x, ty = threadIdx.y;
    const int HW = H_*W_;
    #pragma unroll
    for (int i = ty; i < 32; i += 8) {
        int c = c0 + i, s = s0 + tx;
        if (c < C_ && s < HW) tile[i][tx] = x[(b*C_ + c)*HW + s];
    }
    __syncthreads();
    #pragma unroll
    for (int i = ty; i < 32; i += 8) {
        int s = s0 + i, c = c0 + tx;
        if (s < HW && c < C_) xt[(b*HW + s)*C_ + c] = tile[tx][i];
    }
}

// ---------------------------------------------------------------------------
// Deformable ROI pool, factorized; grid (N, 7): blockIdx.y = ph row
// (7 bins per block -> 7x shorter serial barrier/load chain than 49).
// ---------------------------------------------------------------------------
__global__ void pool_kernel(const float* __restrict__ xt,
                            const float* __restrict__ rois,
                            const float* __restrict__ off,
                            float* __restrict__ out) {
    int n  = blockIdx.x;
    int ph = blockIdx.y;
    int t  = threadIdx.x;

    const float* r = rois + n*5;
    int   b  = (int)r[0];
    float sw = rintf(r[1])*SS_ - 0.5f;
    float sh = rintf(r[2])*SS_ - 0.5f;
    float rw = fmaxf((rintf(r[3]) + 1.0f)*SS_ - 0.5f - sw, 0.1f);
    float rh = fmaxf((rintf(r[4]) + 1.0f)*SS_ - 0.5f - sh, 0.1f);
    float bw = rw / (float)OUT_;
    float bh = rh / (float)OUT_;

    __shared__ float s_wx[8], s_wy[8];
    __shared__ int   s_xa, s_ya, s_nx, s_ny, s_cx, s_cy;

    const int base_b = b * (H_*W_) * C_;

    for (int pw = 0; pw < OUT_; pw++) {
        int bin = ph*OUT_ + pw;
        if (t == 0) {
            float txo = off ? off[n*(2*NBIN) + bin] * TRANS_STD_ : 0.0f;
            float wstart = pw*bw + sw + txo*rw;
            int xa = 1000, xb = -1000, cx = 0;
            #pragma unroll
            for (int j = 0; j < 4; j++) {
                float sx = wstart + (float)j * (bw*0.25f);
                if (sx >= -0.5f && sx <= (float)W_ - 0.5f) {
                    cx++;
                    float xc = fminf(fmaxf(sx, 0.0f), (float)(W_-1));
                    int xi0 = (int)floorf(xc);
                    int xi1 = (int)ceilf(xc);
                    xa = min(xa, xi0); xb = max(xb, xi1);
                }
            }
            int nx = (cx > 0) ? (xb - xa + 1) : 0;
            if (nx > 8) nx = 8;
            float wl[8];
            #pragma unroll
            for (int q = 0; q < 8; q++) wl[q] = 0.0f;
            #pragma unroll
            for (int j = 0; j < 4; j++) {
                float sx = wstart + (float)j * (bw*0.25f);
                if (sx >= -0.5f && sx <= (float)W_ - 0.5f) {
                    float xc = fminf(fmaxf(sx, 0.0f), (float)(W_-1));
                    float x0 = floorf(xc);
                    float dx = xc - x0;
                    int xi0 = (int)x0;
                    int xi1 = (int)ceilf(xc);
                    wl[xi0 - xa] += 1.0f - dx;
                    if (xi1 - xa < 8) wl[xi1 - xa] += dx;
                }
            }
            s_xa = xa; s_nx = nx; s_cx = cx;
            #pragma unroll
            for (int q = 0; q < 8; q++) s_wx[q] = wl[q];
        }
        if (t == 32) {
            float tyo = off ? off[n*(2*NBIN) + NBIN + bin] * TRANS_STD_ : 0.0f;
            float hstart = ph*bh + sh + tyo*rh;
            int ya = 1000, yb = -1000, cy = 0;
            #pragma unroll
            for (int i = 0; i < 4; i++) {
                float sy = hstart + (float)i * (bh*0.25f);
                if (sy >= -0.5f && sy <= (float)H_ - 0.5f) {
                    cy++;
                    float yc = fminf(fmaxf(sy, 0.0f), (float)(H_-1));
                    int yi0 = (int)floorf(yc);
                    int yi1 = (int)ceilf(yc);
                    ya = min(ya, yi0); yb = max(yb, yi1);
                }
            }
            int ny = (cy > 0) ? (yb - ya + 1) : 0;
            if (ny > 8) ny = 8;
            float wl[8];
            #pragma unroll
            for (int q = 0; q < 8; q++) wl[q] = 0.0f;
            #pragma unroll
            for (int i = 0; i < 4; i++) {
                float sy = hstart + (float)i * (bh*0.25f);
                if (sy >= -0.5f && sy <= (float)H_ - 0.5f) {
                    float yc = fminf(fmaxf(sy, 0.0f), (float)(H_-1));
                    float y0 = floorf(yc);
                    float dy = yc - y0;
                    int yi0 = (int)y0;
                    int yi1 = (int)ceilf(yc);
                    wl[yi0 - ya] += 1.0f - dy;
                    if (yi1 - ya < 8) wl[yi1 - ya] += dy;
                }
            }
            s_ya = ya; s_ny = ny; s_cy = cy;
            #pragma unroll
            for (int q = 0; q < 8; q++) s_wy[q] = wl[q];
        }
        __syncthreads();

        float inv = 1.0f / fmaxf((float)(s_cx * s_cy), 1.0f);
        float acc = 0.0f;
        int ny = s_ny, nx = s_nx, ya = s_ya, xa = s_xa;
        for (int iy = 0; iy < ny; iy++) {
            float wy = s_wy[iy];
            if (wy == 0.0f) continue;
            int rowoff = base_b + ((ya + iy)*W_ + xa)*C_ + t;
            for (int ix = 0; ix < nx; ix++) {
                float wv = wy * s_wx[ix];
                if (wv != 0.0f) acc += wv * xt[rowoff + ix*C_];
            }
        }
        out[n*IN_ + t*NBIN + bin] = acc * inv;
        __syncthreads();
    }
}

// ---------------------------------------------------------------------------
// fp32 -> bf16 hi/lo pack
// ---------------------------------------------------------------------------
__device__ __forceinline__ void packpair(float e, float o, uint32_t& h, uint32_t& l) {
    asm("cvt.rn.bf16x2.f32 %0, %1, %2;" : "=r"(h) : "f"(o), "f"(e));
    float re = e - __uint_as_float(h << 16);
    float ro = o - __uint_as_float(h & 0xffff0000u);
    asm("cvt.rn.bf16x2.f32 %0, %1, %2;" : "=r"(l) : "f"(ro), "f"(re));
}

// ---------------------------------------------------------------------------
// Weight -> fragment-ordered bf16 hi/lo.  uint4 id = ((mb*KT+kt)*8+wt)*32+lane
// ---------------------------------------------------------------------------
__global__ void conv_frag_w(const float* __restrict__ Wm, uint4* __restrict__ hi,
                            uint4* __restrict__ lo, int K, int total) {
    int tid = blockIdx.x * 256 + threadIdx.x;
    if (tid >= total) return;
    int lane = tid & 31;
    int rest = tid >> 5;
    int wt = rest & 7; rest >>= 3;
    int KT = K >> 4;
    int kt = rest % KT;
    int mb = rest / KT;
    int m0 = mb*128 + wt*16 + (lane >> 2);
    int k0 = kt*16 + (lane & 3)*2;
    uint4 h, l;
    const float* p00 = Wm + (size_t)m0*K + k0;
    const float* p10 = Wm + (size_t)(m0+8)*K + k0;
    packpair(p00[0], p00[1], h.x, l.x);
    packpair(p00[8], p00[9], h.y, l.y);
    packpair(p10[0], p10[1], h.z, l.z);
    packpair(p10[8], p10[9], h.w, l.w);
    hi[tid] = h; lo[tid] = l;
}

// ---------------------------------------------------------------------------
// Activation -> fragment-ordered bf16 hi/lo.  uint4 id = ((nb*KT+kt)*8+at)*32+lane
// ---------------------------------------------------------------------------
__global__ void conv_frag_a(const float* __restrict__ A, uint4* __restrict__ hi,
                            uint4* __restrict__ lo, int K, int total) {
    int tid = blockIdx.x * 256 + threadIdx.x;
    if (tid >= total) return;
    int lane = tid & 31;
    int rest = tid >> 5;
    int at = rest & 7; rest >>= 3;
    int KT = K >> 4;
    int kt = rest % KT;
    int nb = rest / KT;
    int m0 = nb*128 + at*16 + (lane >> 2);
    int k0 = kt*16 + (lane & 3)*2;
    uint4 h, l;
    const float* p00 = A + (size_t)m0*K + k0;
    const float* p10 = A + (size_t)(m0+8)*K + k0;
    packpair(p00[0], p00[1], h.x, l.x);
    packpair(p10[0], p10[1], h.y, l.y);
    packpair(p00[8], p00[9], h.z, l.z);
    packpair(p10[8], p10[9], h.w, l.w);
    hi[tid] = h; lo[tid] = l;
}

// ---------------------------------------------------------------------------
// bf16 3-term mma.sync GEMM, split-K, no smem.
// ---------------------------------------------------------------------------
__device__ __forceinline__ void mma_bf16(float* c, const uint4& a,
                                         uint32_t b0, uint32_t b1) {
    asm volatile(
        "mma.sync.aligned.m16n8k16.row.col.f32.bf16.bf16.f32 "
        "{%0,%1,%2,%3}, {%4,%5,%6,%7}, {%8,%9}, {%0,%1,%2,%3};"
        : "+f"(c[0]), "+f"(c[1]), "+f"(c[2]), "+f"(c[3])
        : "r"(a.x), "r"(a.y), "r"(a.z), "r"(a.w), "r"(b0), "r"(b1));
}

__global__ __launch_bounds__(256, 2) void gemm_bf16(
    const uint4* __restrict__ Ahi, const uint4* __restrict__ Alo,
    const uint4* __restrict__ Whi, const uint4* __restrict__ Wlo,
    float* __restrict__ part, int M, int KT, int Kc16) {
    int tid = threadIdx.x, wid = tid >> 5, lane = tid & 31;
    int wr = wid >> 1, wc = wid & 1;
    int mb = blockIdx.x, nb = blockIdx.y, s = blockIdx.z;

    float acc[2][8][4];
    #pragma unroll
    for (int i = 0; i < 2; i++)
        #pragma unroll
        for (int j = 0; j < 8; j++)
            #pragma unroll
            for (int q = 0; q < 4; q++) acc[i][j][q] = 0.0f;

    int kt0 = s * Kc16;
    int at0 = wr*2;

    for (int t = 0; t < Kc16; t++) {
        int kt = kt0 + t;
        int baseA = ((nb*KT + kt)*8)*32 + lane;
        uint4 ah0 = Ahi[baseA + at0*32];
        uint4 ah1 = Ahi[baseA + (at0+1)*32];
        uint4 al0 = Alo[baseA + at0*32];
        uint4 al1 = Alo[baseA + (at0+1)*32];
        int baseW = ((mb*KT + kt)*8)*32 + lane + wc*4*32;
        #pragma unroll
        for (int wt = 0; wt < 4; wt++) {
            uint4 wh = Whi[baseW + wt*32];
            uint4 wl = Wlo[baseW + wt*32];
            int nf = wt*2;
            mma_bf16(acc[0][nf],   ah0, wh.x, wh.y);
            mma_bf16(acc[0][nf+1], ah0, wh.z, wh.w);
            mma_bf16(acc[1][nf],   ah1, wh.x, wh.y);
            mma_bf16(acc[1][nf+1], ah1, wh.z, wh.w);
            mma_bf16(acc[0][nf],   ah0, wl.x, wl.y);
            mma_bf16(acc[0][nf+1], ah0, wl.z, wl.w);
            mma_bf16(acc[1][nf],   ah1, wl.x, wl.y);
            mma_bf16(acc[1][nf+1], ah1, wl.z, wl.w);
            mma_bf16(acc[0][nf],   al0, wh.x, wh.y);
            mma_bf16(acc[0][nf+1], al0, wh.z, wh.w);
            mma_bf16(acc[1][nf],   al1, wh.x, wh.y);
            mma_bf16(acc[1][nf+1], al1, wh.z, wh.w);
        }
    }

    float* p = part + (size_t)s * N_ * M;
    #pragma unroll
    for (int i = 0; i < 2; i++) {
        int row = nb*128 + wr*32 + i*16 + (lane >> 2);
        #pragma unroll
        for (int nf = 0; nf < 8; nf++) {
            int col = mb*128 + wc*64 + nf*8 + (lane & 3)*2;
            *(float2*)(p + (size_t)row*M + col)     = make_float2(acc[i][nf][0], acc[i][nf][1]);
            *(float2*)(p + (size_t)(row+8)*M + col) = make_float2(acc[i][nf][2], acc[i][nf][3]);
        }
    }
}

// ---------------------------------------------------------------------------
// Reduce split-K partials + bias (+ optional relu), float4
// ---------------------------------------------------------------------------
__global__ void reduce_kernel(const float4* __restrict__ part,
                              const float* __restrict__ bias,
                              float4* __restrict__ C, int M4, int S, int relu) {
    int idx = blockIdx.x * 256 + threadIdx.x;
    int col4 = idx % M4;
    const float4* bp = (const float4*)bias;
    float4 acc = bp[col4];
    for (int s = 0; s < S; s++) {
        float4 v = part[(size_t)s*N_*M4 + idx];
        acc.x += v.x; acc.y += v.y; acc.z += v.z; acc.w += v.w;
    }
    if (relu) {
        acc.x = fmaxf(acc.x, 0.0f); acc.y = fmaxf(acc.y, 0.0f);
        acc.z = fmaxf(acc.z, 0.0f); acc.w = fmaxf(acc.w, 0.0f);
    }
    C[idx] = acc;
}

// ---------------------------------------------------------------------------
// off3 head
// ---------------------------------------------------------------------------
__global__ void off3_kernel(const float* __restrict__ h,
                            const float* __restrict__ w3,
                            const float* __restrict__ b3,
                            float* __restrict__ out) {
    int n = blockIdx.x;
    int tid = threadIdx.x;
    __shared__ float sh[DFC_];
    ((float4*)sh)[tid] = ((const float4*)(h + n*DFC_))[tid];
    __syncthreads();
    int warp = tid >> 5, lane = tid & 31;
    for (int o = warp; o < 2*NBIN; o += 8) {
        const float4* w = (const float4*)(w3 + o*DFC_);
        float acc = 0.0f;
        #pragma unroll
        for (int i = lane; i < DFC_/4; i += 32) {
            float4 wv = w[i];
            float4 av = ((const float4*)sh)[i];
            acc += wv.x*av.x + wv.y*av.y + wv.z*av.z + wv.w*av.w;
        }
        #pragma unroll
        for (int d = 16; d > 0; d >>= 1) acc += __shfl_down_sync(0xffffffffu, acc, d);
        if (lane == 0) out[n*(2*NBIN) + o] = acc + b3[o];
    }
}

// ---------------------------------------------------------------------------
// box head
// ---------------------------------------------------------------------------
__global__ void box_kernel(const float* __restrict__ f2,
                           const float* __restrict__ bw,
                           const float* __restrict__ bb,
                           float* __restrict__ out) {
    int n = blockIdx.x;
    int w = threadIdx.x >> 5;
    int lane = threadIdx.x & 31;
    float acc = 0.0f;
    for (int k = lane; k < FCC_; k += 32) acc += f2[n*FCC_ + k]*bw[w*FCC_ + k];
    #pragma unroll
    for (int o = 16; o > 0; o >>= 1) acc += __shfl_down_sync(0xffffffffu, acc, o);
    if (lane == 0) out[n*4 + w] = acc + bb[w];
}

// ---------------------------------------------------------------------------
extern "C" void kernel_launch(void* const* d_in, const int* in_sizes, int n_in,
                              void* d_out, int out_size) {
    const float* x      = (const float*)d_in[0];
    const float* rois   = (const float*)d_in[1];
    const float* off_w1 = (const float*)d_in[2];
    const float* off_b1 = (const float*)d_in[3];
    const float* off_w2 = (const float*)d_in[4];
    const float* off_b2 = (const float*)d_in[5];
    const float* off_w3 = (const float*)d_in[6];
    const float* off_b3 = (const float*)d_in[7];
    const float* fc1_w  = (const float*)d_in[8];
    const float* fc1_b  = (const float*)d_in[9];
    const float* fc2_w  = (const float*)d_in[10];
    const float* fc2_b  = (const float*)d_in[11];
    const float* box_w  = (const float*)d_in[12];
    const float* box_b  = (const float*)d_in[13];
    float* out = (float*)d_out;

    float *xt, *p0, *h1, *h2, *offb, *p1, *f1, *f2, *part;
    uint4 *w1hi, *w1lo, *w2hi, *w2lo, *q1hi, *q1lo, *q2hi, *q2lo, *ahi, *alo;
    cudaGetSymbolAddress((void**)&xt,   g_xt);
    cudaGetSymbolAddress((void**)&p0,   g_p0);
    cudaGetSymbolAddress((void**)&h1,   g_h1);
    cudaGetSymbolAddress((void**)&h2,   g_h2);
    cudaGetSymbolAddress((void**)&offb, g_off);
    cudaGetSymbolAddress((void**)&p1,   g_p1);
    cudaGetSymbolAddress((void**)&f1,   g_f1);
    cudaGetSymbolAddress((void**)&f2,   g_f2);
    cudaGetSymbolAddress((void**)&part, g_part);
    cudaGetSymbolAddress((void**)&w1hi, g_w1hi);
    cudaGetSymbolAddress((void**)&w1lo, g_w1lo);
    cudaGetSymbolAddress((void**)&w2hi, g_w2hi);
    cudaGetSymbolAddress((void**)&w2lo, g_w2lo);
    cudaGetSymbolAddress((void**)&q1hi, g_q1hi);
    cudaGetSymbolAddress((void**)&q1lo, g_q1lo);
    cudaGetSymbolAddress((void**)&q2hi, g_q2hi);
    cudaGetSymbolAddress((void**)&q2lo, g_q2lo);
    cudaGetSymbolAddress((void**)&ahi,  g_ahi);
    cudaGetSymbolAddress((void**)&alo,  g_alo);

    // Weight conversions (single stream; independent of data path)
    conv_frag_w<<<6272, 256>>>(off_w1, w1hi, w1lo, IN_,  1605632);
    conv_frag_w<<<512,  256>>>(off_w2, w2hi, w2lo, DFC_, 131072);
    conv_frag_w<<<3136, 256>>>(fc1_w,  q1hi, q1lo, IN_,  802816);
    conv_frag_w<<<128,  256>>>(fc2_w,  q2hi, q2lo, FCC_, 32768);

    // 1. x -> xt
    {
        dim3 grid((H_*W_ + 31)/32, (C_ + 31)/32, B_);
        dim3 block(32, 8);
        transpose_kernel<<<grid, block>>>(x, xt);
    }
    // 2. pool (zero offsets) -> p0, convert
    pool_kernel<<<dim3(N_, OUT_), 256>>>(xt, rois, nullptr, p0);
    conv_frag_a<<<1568, 256>>>(p0, ahi, alo, IN_, 401408);

    // 3. h1 = relu(p0 @ off_w1^T + b1)  [256x1024, K=12544], S=14 (Kc16=56)
    gemm_bf16<<<dim3(8, 2, 14), 256>>>(ahi, alo, w1hi, w1lo, part, DFC_, 784, 56);
    reduce_kernel<<<(N_*DFC_/4)/256, 256>>>((const float4*)part, off_b1, (float4*)h1, DFC_/4, 14, 1);

    // 4. h2 = relu(h1 @ off_w2^T + b2)  [256x1024, K=1024], S=8 (Kc16=8)
    conv_frag_a<<<128, 256>>>(h1, ahi, alo, DFC_, 32768);
    gemm_bf16<<<dim3(8, 2, 8), 256>>>(ahi, alo, w2hi, w2lo, part, DFC_, 64, 8);
    reduce_kernel<<<(N_*DFC_/4)/256, 256>>>((const float4*)part, off_b2, (float4*)h2, DFC_/4, 8, 1);

    // 5. off = h2 @ off_w3^T + b3       [256x98]
    off3_kernel<<<N_, 256>>>(h2, off_w3, off_b3, offb);

    // 6. pool (learned offsets) -> p1, convert
    pool_kernel<<<dim3(N_, OUT_), 256>>>(xt, rois, offb, p1);
    conv_frag_a<<<1568, 256>>>(p1, ahi, alo, IN_, 401408);

    // 7. f1 = relu(p1 @ fc1_w^T + b)    [256x512, K=12544], S=28 (Kc16=28)
    gemm_bf16<<<dim3(4, 2, 28), 256>>>(ahi, alo, q1hi, q1lo, part, FCC_, 784, 28);
    reduce_kernel<<<(N_*FCC_/4)/256, 256>>>((const float4*)part, fc1_b, (float4*)f1, FCC_/4, 28, 1);

    // 8. f2 = relu(f1 @ fc2_w^T + b)    [256x512, K=512], S=16 (Kc16=2)
    conv_frag_a<<<64, 256>>>(f1, ahi, alo, FCC_, 16384);
    gemm_bf16<<<dim3(4, 2, 16), 256>>>(ahi, alo, q2hi, q2lo, part, FCC_, 32, 2);
    reduce_kernel<<<(N_*FCC_/4)/256, 256>>>((const float4*)part, fc2_b, (float4*)f2, FCC_/4, 16, 1);

    // 9. out = f2 @ box_w^T + box_b     [256x4]
    box_kernel<<<N_, 128>>>(f2, box_w, box_b, out);
}

// round 14
// speedup vs baseline: 2.8112x; 1.0430x over previous
#include <cuda_runtime.h>
#include <cuda_bf16.h>
#include <cstdint>

// Problem constants
#define B_ 8
#define C_ 256
#define H_ 25
#define W_ 25
#define N_ 256
#define OUT_ 7
#define NBIN 49
#define IN_ 12544   // C*7*7
#define DFC_ 1024
#define FCC_ 512
#define SS_ (25.0f/255.0f)
#define TRANS_STD_ 0.1f

// fp32 scratch
__device__ float g_xt[B_*H_*W_*C_];
__device__ float g_p0[N_*IN_];
__device__ float g_h1[N_*DFC_];
__device__ float g_h2[N_*DFC_];
__device__ float g_off[N_*2*NBIN];
__device__ float g_p1[N_*IN_];
__device__ float g_f1[N_*FCC_];
__device__ float g_f2[N_*FCC_];
__device__ float g_part[3670016];      // split-K partials (max 14*256*1024 == 28*256*512)

// bf16 hi/lo fragment-ordered buffers (uint4 = 4 regs x 2 bf16 = 8 elements)
__device__ uint4 g_w1hi[1605632], g_w1lo[1605632];   // off_w1 1024x12544
__device__ uint4 g_w2hi[131072],  g_w2lo[131072];    // off_w2 1024x1024
__device__ uint4 g_q1hi[802816],  g_q1lo[802816];    // fc1_w  512x12544
__device__ uint4 g_q2hi[32768],   g_q2lo[32768];     // fc2_w  512x512
__device__ uint4 g_ahi[401408],   g_alo[401408];     // activations (256x12544 / 8)

// ---------------------------------------------------------------------------
// Transpose x (B,C,H,W) -> xt (B,H*W,C)
// ---------------------------------------------------------------------------
__global__ void transpose_kernel(const float* __restrict__ x, float* __restrict__ xt) {
    __shared__ float tile[32][33];
    int b  = blockIdx.z;
    int s0 = blockIdx.x * 32;
    int c0 = blockIdx.y * 32;
    int tx = threadIdx.x, ty = threadIdx.y;
    const int HW = H_*W_;
    #pragma unroll
    for (int i = ty; i < 32; i += 8) {
        int c = c0 + i, s = s0 + tx;
        if (c < C_ && s < HW) tile[i][tx] = x[(b*C_ + c)*HW + s];
    }
    __syncthreads();
    #pragma unroll
    for (int i = ty; i < 32; i += 8) {
        int s = s0 + i, c = c0 + tx;
        if (s < HW && c < C_) xt[(b*HW + s)*C_ + c] = tile[tx][i];
    }
}

// ---------------------------------------------------------------------------
// Deformable ROI pool, factorized; grid (N, 7)
// ---------------------------------------------------------------------------
__global__ void pool_kernel(const float* __restrict__ xt,
                            const float* __restrict__ rois,
                            const float* __restrict__ off,
                            float* __restrict__ out) {
    int n  = blockIdx.x;
    int ph = blockIdx.y;
    int t  = threadIdx.x;

    const float* r = rois + n*5;
    int   b  = (int)r[0];
    float sw = rintf(r[1])*SS_ - 0.5f;
    float sh = rintf(r[2])*SS_ - 0.5f;
    float rw = fmaxf((rintf(r[3]) + 1.0f)*SS_ - 0.5f - sw, 0.1f);
    float rh = fmaxf((rintf(r[4]) + 1.0f)*SS_ - 0.5f - sh, 0.1f);
    float bw = rw / (float)OUT_;
    float bh = rh / (float)OUT_;

    __shared__ float s_wx[8], s_wy[8];
    __shared__ int   s_xa, s_ya, s_nx, s_ny, s_cx, s_cy;

    const int base_b = b * (H_*W_) * C_;

    for (int pw = 0; pw < OUT_; pw++) {
        int bin = ph*OUT_ + pw;
        if (t == 0) {
            float txo = off ? off[n*(2*NBIN) + bin] * TRANS_STD_ : 0.0f;
            float wstart = pw*bw + sw + txo*rw;
            int xa = 1000, xb = -1000, cx = 0;
            #pragma unroll
            for (int j = 0; j < 4; j++) {
                float sx = wstart + (float)j * (bw*0.25f);
                if (sx >= -0.5f && sx <= (float)W_ - 0.5f) {
                    cx++;
                    float xc = fminf(fmaxf(sx, 0.0f), (float)(W_-1));
                    int xi0 = (int)floorf(xc);
                    int xi1 = (int)ceilf(xc);
                    xa = min(xa, xi0); xb = max(xb, xi1);
                }
            }
            int nx = (cx > 0) ? (xb - xa + 1) : 0;
            if (nx > 8) nx = 8;
            float wl[8];
            #pragma unroll
            for (int q = 0; q < 8; q++) wl[q] = 0.0f;
            #pragma unroll
            for (int j = 0; j < 4; j++) {
                float sx = wstart + (float)j * (bw*0.25f);
                if (sx >= -0.5f && sx <= (float)W_ - 0.5f) {
                    float xc = fminf(fmaxf(sx, 0.0f), (float)(W_-1));
                    float x0 = floorf(xc);
                    float dx = xc - x0;
                    int xi0 = (int)x0;
                    int xi1 = (int)ceilf(xc);
                    wl[xi0 - xa] += 1.0f - dx;
                    if (xi1 - xa < 8) wl[xi1 - xa] += dx;
                }
            }
            s_xa = xa; s_nx = nx; s_cx = cx;
            #pragma unroll
            for (int q = 0; q < 8; q++) s_wx[q] = wl[q];
        }
        if (t == 32) {
            float tyo = off ? off[n*(2*NBIN) + NBIN + bin] * TRANS_STD_ : 0.0f;
            float hstart = ph*bh + sh + tyo*rh;
            int ya = 1000, yb = -1000, cy = 0;
            #pragma unroll
            for (int i = 0; i < 4; i++) {
                float sy = hstart + (float)i * (bh*0.25f);
                if (sy >= -0.5f && sy <= (float)H_ - 0.5f) {
                    cy++;
                    float yc = fminf(fmaxf(sy, 0.0f), (float)(H_-1));
                    int yi0 = (int)floorf(yc);
                    int yi1 = (int)ceilf(yc);
                    ya = min(ya, yi0); yb = max(yb, yi1);
                }
            }
            int ny = (cy > 0) ? (yb - ya + 1) : 0;
            if (ny > 8) ny = 8;
            float wl[8];
            #pragma unroll
            for (int q = 0; q < 8; q++) wl[q] = 0.0f;
            #pragma unroll
            for (int i = 0; i < 4; i++) {
                float sy = hstart + (float)i * (bh*0.25f);
                if (sy >= -0.5f && sy <= (float)H_ - 0.5f) {
                    float yc = fminf(fmaxf(sy, 0.0f), (float)(H_-1));
                    float y0 = floorf(yc);
                    float dy = yc - y0;
                    int yi0 = (int)y0;
                    int yi1 = (int)ceilf(yc);
                    wl[yi0 - ya] += 1.0f - dy;
                    if (yi1 - ya < 8) wl[yi1 - ya] += dy;
                }
            }
            s_ya = ya; s_ny = ny; s_cy = cy;
            #pragma unroll
            for (int q = 0; q < 8; q++) s_wy[q] = wl[q];
        }
        __syncthreads();

        float inv = 1.0f / fmaxf((float)(s_cx * s_cy), 1.0f);
        float acc = 0.0f;
        int ny = s_ny, nx = s_nx, ya = s_ya, xa = s_xa;
        for (int iy = 0; iy < ny; iy++) {
            float wy = s_wy[iy];
            if (wy == 0.0f) continue;
            int rowoff = base_b + ((ya + iy)*W_ + xa)*C_ + t;
            for (int ix = 0; ix < nx; ix++) {
                float wv = wy * s_wx[ix];
                if (wv != 0.0f) acc += wv * xt[rowoff + ix*C_];
            }
        }
        out[n*IN_ + t*NBIN + bin] = acc * inv;
        __syncthreads();
    }
}

// ---------------------------------------------------------------------------
// fp32 -> bf16 hi/lo pack
// ---------------------------------------------------------------------------
__device__ __forceinline__ void packpair(float e, float o, uint32_t& h, uint32_t& l) {
    asm("cvt.rn.bf16x2.f32 %0, %1, %2;" : "=r"(h) : "f"(o), "f"(e));
    float re = e - __uint_as_float(h << 16);
    float ro = o - __uint_as_float(h & 0xffff0000u);
    asm("cvt.rn.bf16x2.f32 %0, %1, %2;" : "=r"(l) : "f"(ro), "f"(re));
}

// ---------------------------------------------------------------------------
// Weight -> fragment-ordered bf16 hi/lo.  uint4 id = ((mb*KT+kt)*8+wt)*32+lane
// ---------------------------------------------------------------------------
__global__ void conv_frag_w(const float* __restrict__ Wm, uint4* __restrict__ hi,
                            uint4* __restrict__ lo, int K, int total) {
    int tid = blockIdx.x * 256 + threadIdx.x;
    if (tid >= total) return;
    int lane = tid & 31;
    int rest = tid >> 5;
    int wt = rest & 7; rest >>= 3;
    int KT = K >> 4;
    int kt = rest % KT;
    int mb = rest / KT;
    int m0 = mb*128 + wt*16 + (lane >> 2);
    int k0 = kt*16 + (lane & 3)*2;
    uint4 h, l;
    const float* p00 = Wm + (size_t)m0*K + k0;
    const float* p10 = Wm + (size_t)(m0+8)*K + k0;
    packpair(p00[0], p00[1], h.x, l.x);
    packpair(p00[8], p00[9], h.y, l.y);
    packpair(p10[0], p10[1], h.z, l.z);
    packpair(p10[8], p10[9], h.w, l.w);
    hi[tid] = h; lo[tid] = l;
}

// ---------------------------------------------------------------------------
// Activation -> fragment-ordered bf16 hi/lo.  uint4 id = ((nb*KT+kt)*8+at)*32+lane
// ---------------------------------------------------------------------------
__global__ void conv_frag_a(const float* __restrict__ A, uint4* __restrict__ hi,
                            uint4* __restrict__ lo, int K, int total) {
    int tid = blockIdx.x * 256 + threadIdx.x;
    if (tid >= total) return;
    int lane = tid & 31;
    int rest = tid >> 5;
    int at = rest & 7; rest >>= 3;
    int KT = K >> 4;
    int kt = rest % KT;
    int nb = rest / KT;
    int m0 = nb*128 + at*16 + (lane >> 2);
    int k0 = kt*16 + (lane & 3)*2;
    uint4 h, l;
    const float* p00 = A + (size_t)m0*K + k0;
    const float* p10 = A + (size_t)(m0+8)*K + k0;
    packpair(p00[0], p00[1], h.x, l.x);
    packpair(p10[0], p10[1], h.y, l.y);
    packpair(p00[8], p00[9], h.z, l.z);
    packpair(p10[8], p10[9], h.w, l.w);
    hi[tid] = h; lo[tid] = l;
}

// ---------------------------------------------------------------------------
// bf16 3-term mma.sync GEMM, split-K, cp.async double-buffered smem staging.
// Per kt (16 k-elems) the four operand blocks (Ahi, Alo, Whi, Wlo) are each
// 256 contiguous uint4 (4 KB); staged by all 256 threads (1 cp.async each),
// compute reads conflict-free LDS.128.
// ---------------------------------------------------------------------------
__device__ __forceinline__ void mma_bf16(float* c, const uint4& a,
                                         uint32_t b0, uint32_t b1) {
    asm volatile(
        "mma.sync.aligned.m16n8k16.row.col.f32.bf16.bf16.f32 "
        "{%0,%1,%2,%3}, {%4,%5,%6,%7}, {%8,%9}, {%0,%1,%2,%3};"
        : "+f"(c[0]), "+f"(c[1]), "+f"(c[2]), "+f"(c[3])
        : "r"(a.x), "r"(a.y), "r"(a.z), "r"(a.w), "r"(b0), "r"(b1));
}

__device__ __forceinline__ void cp16(void* smem, const void* g) {
    uint32_t s = (uint32_t)__cvta_generic_to_shared(smem);
    asm volatile("cp.async.cg.shared.global [%0], [%1], 16;" :: "r"(s), "l"(g));
}
__device__ __forceinline__ void cp_commit() {
    asm volatile("cp.async.commit_group;" ::: "memory");
}
__device__ __forceinline__ void cp_wait1() {
    asm volatile("cp.async.wait_group 1;" ::: "memory");
}
__device__ __forceinline__ void cp_wait0() {
    asm volatile("cp.async.wait_group 0;" ::: "memory");
}

__global__ __launch_bounds__(256, 2) void gemm_bf16(
    const uint4* __restrict__ Ahi, const uint4* __restrict__ Alo,
    const uint4* __restrict__ Whi, const uint4* __restrict__ Wlo,
    float* __restrict__ part, int M, int KT, int Kc16) {
    __shared__ uint4 sAh[2][256], sAl[2][256], sWh[2][256], sWl[2][256];

    int tid = threadIdx.x, wid = tid >> 5, lane = tid & 31;
    int wr = wid >> 1, wc = wid & 1;
    int mb = blockIdx.x, nb = blockIdx.y, s = blockIdx.z;

    float acc[2][8][4];
    #pragma unroll
    for (int i = 0; i < 2; i++)
        #pragma unroll
        for (int j = 0; j < 8; j++)
            #pragma unroll
            for (int q = 0; q < 4; q++) acc[i][j][q] = 0.0f;

    int kt0 = s * Kc16;
    int at0 = wr*2;

    // stage kt0 into buffer 0
    {
        size_t a_off = ((size_t)(nb*KT + kt0)*8)*32 + tid;
        size_t w_off = ((size_t)(mb*KT + kt0)*8)*32 + tid;
        cp16(&sAh[0][tid], Ahi + a_off);
        cp16(&sAl[0][tid], Alo + a_off);
        cp16(&sWh[0][tid], Whi + w_off);
        cp16(&sWl[0][tid], Wlo + w_off);
        cp_commit();
    }

    for (int t = 0; t < Kc16; t++) {
        int buf = t & 1;
        if (t + 1 < Kc16) {
            int kt = kt0 + t + 1;
            int nbuf = (t + 1) & 1;
            size_t a_off = ((size_t)(nb*KT + kt)*8)*32 + tid;
            size_t w_off = ((size_t)(mb*KT + kt)*8)*32 + tid;
            cp16(&sAh[nbuf][tid], Ahi + a_off);
            cp16(&sAl[nbuf][tid], Alo + a_off);
            cp16(&sWh[nbuf][tid], Whi + w_off);
            cp16(&sWl[nbuf][tid], Wlo + w_off);
            cp_commit();
            cp_wait1();
        } else {
            cp_wait0();
        }
        __syncthreads();

        uint4 ah0 = sAh[buf][at0*32 + lane];
        uint4 ah1 = sAh[buf][at0*32 + 32 + lane];
        uint4 al0 = sAl[buf][at0*32 + lane];
        uint4 al1 = sAl[buf][at0*32 + 32 + lane];
        #pragma unroll
        for (int wt = 0; wt < 4; wt++) {
            uint4 wh = sWh[buf][wc*128 + wt*32 + lane];
            uint4 wl = sWl[buf][wc*128 + wt*32 + lane];
            int nf = wt*2;
            mma_bf16(acc[0][nf],   ah0, wh.x, wh.y);
            mma_bf16(acc[0][nf+1], ah0, wh.z, wh.w);
            mma_bf16(acc[1][nf],   ah1, wh.x, wh.y);
            mma_bf16(acc[1][nf+1], ah1, wh.z, wh.w);
            mma_bf16(acc[0][nf],   ah0, wl.x, wl.y);
            mma_bf16(acc[0][nf+1], ah0, wl.z, wl.w);
            mma_bf16(acc[1][nf],   ah1, wl.x, wl.y);
            mma_bf16(acc[1][nf+1], ah1, wl.z, wl.w);
            mma_bf16(acc[0][nf],   al0, wh.x, wh.y);
            mma_bf16(acc[0][nf+1], al0, wh.z, wh.w);
            mma_bf16(acc[1][nf],   al1, wh.x, wh.y);
            mma_bf16(acc[1][nf+1], al1, wh.z, wh.w);
        }
        __syncthreads();
    }

    float* p = part + (size_t)s * N_ * M;
    #pragma unroll
    for (int i = 0; i < 2; i++) {
        int row = nb*128 + wr*32 + i*16 + (lane >> 2);
        #pragma unroll
        for (int nf = 0; nf < 8; nf++) {
            int col = mb*128 + wc*64 + nf*8 + (lane & 3)*2;
            *(float2*)(p + (size_t)row*M + col)     = make_float2(acc[i][nf][0], acc[i][nf][1]);
            *(float2*)(p + (size_t)(row+8)*M + col) = make_float2(acc[i][nf][2], acc[i][nf][3]);
        }
    }
}

// ---------------------------------------------------------------------------
// Reduce split-K partials + bias (+ optional relu), float4
// ---------------------------------------------------------------------------
__global__ void reduce_kernel(const float4* __restrict__ part,
                              const float* __restrict__ bias,
                              float4* __restrict__ C, int M4, int S, int relu) {
    int idx = blockIdx.x * 256 + threadIdx.x;
    int col4 = idx % M4;
    const float4* bp = (const float4*)bias;
    float4 acc = bp[col4];
    for (int s = 0; s < S; s++) {
        float4 v = part[(size_t)s*N_*M4 + idx];
        acc.x += v.x; acc.y += v.y; acc.z += v.z; acc.w += v.w;
    }
    if (relu) {
        acc.x = fmaxf(acc.x, 0.0f); acc.y = fmaxf(acc.y, 0.0f);
        acc.z = fmaxf(acc.z, 0.0f); acc.w = fmaxf(acc.w, 0.0f);
    }
    C[idx] = acc;
}

// ---------------------------------------------------------------------------
// off3 head
// ---------------------------------------------------------------------------
__global__ void off3_kernel(const float* __restrict__ h,
                            const float* __restrict__ w3,
                            const float* __restrict__ b3,
                            float* __restrict__ out) {
    int n = blockIdx.x;
    int tid = threadIdx.x;
    __shared__ float sh[DFC_];
    ((float4*)sh)[tid] = ((const float4*)(h + n*DFC_))[tid];
    __syncthreads();
    int warp = tid >> 5, lane = tid & 31;
    for (int o = warp; o < 2*NBIN; o += 8) {
        const float4* w = (const float4*)(w3 + o*DFC_);
        float acc = 0.0f;
        #pragma unroll
        for (int i = lane; i < DFC_/4; i += 32) {
            float4 wv = w[i];
            float4 av = ((const float4*)sh)[i];
            acc += wv.x*av.x + wv.y*av.y + wv.z*av.z + wv.w*av.w;
        }
        #pragma unroll
        for (int d = 16; d > 0; d >>= 1) acc += __shfl_down_sync(0xffffffffu, acc, d);
        if (lane == 0) out[n*(2*NBIN) + o] = acc + b3[o];
    }
}

// ---------------------------------------------------------------------------
// box head
// ---------------------------------------------------------------------------
__global__ void box_kernel(const float* __restrict__ f2,
                           const float* __restrict__ bw,
                           const float* __restrict__ bb,
                           float* __restrict__ out) {
    int n = blockIdx.x;
    int w = threadIdx.x >> 5;
    int lane = threadIdx.x & 31;
    float acc = 0.0f;
    for (int k = lane; k < FCC_; k += 32) acc += f2[n*FCC_ + k]*bw[w*FCC_ + k];
    #pragma unroll
    for (int o = 16; o > 0; o >>= 1) acc += __shfl_down_sync(0xffffffffu, acc, o);
    if (lane == 0) out[n*4 + w] = acc + bb[w];
}

// ---------------------------------------------------------------------------
extern "C" void kernel_launch(void* const* d_in, const int* in_sizes, int n_in,
                              void* d_out, int out_size) {
    const float* x      = (const float*)d_in[0];
    const float* rois   = (const float*)d_in[1];
    const float* off_w1 = (const float*)d_in[2];
    const float* off_b1 = (const float*)d_in[3];
    const float* off_w2 = (const float*)d_in[4];
    const float* off_b2 = (const float*)d_in[5];
    const float* off_w3 = (const float*)d_in[6];
    const float* off_b3 = (const float*)d_in[7];
    const float* fc1_w  = (const float*)d_in[8];
    const float* fc1_b  = (const float*)d_in[9];
    const float* fc2_w  = (const float*)d_in[10];
    const float* fc2_b  = (const float*)d_in[11];
    const float* box_w  = (const float*)d_in[12];
    const float* box_b  = (const float*)d_in[13];
    float* out = (float*)d_out;

    float *xt, *p0, *h1, *h2, *offb, *p1, *f1, *f2, *part;
    uint4 *w1hi, *w1lo, *w2hi, *w2lo, *q1hi, *q1lo, *q2hi, *q2lo, *ahi, *alo;
    cudaGetSymbolAddress((void**)&xt,   g_xt);
    cudaGetSymbolAddress((void**)&p0,   g_p0);
    cudaGetSymbolAddress((void**)&h1,   g_h1);
    cudaGetSymbolAddress((void**)&h2,   g_h2);
    cudaGetSymbolAddress((void**)&offb, g_off);
    cudaGetSymbolAddress((void**)&p1,   g_p1);
    cudaGetSymbolAddress((void**)&f1,   g_f1);
    cudaGetSymbolAddress((void**)&f2,   g_f2);
    cudaGetSymbolAddress((void**)&part, g_part);
    cudaGetSymbolAddress((void**)&w1hi, g_w1hi);
    cudaGetSymbolAddress((void**)&w1lo, g_w1lo);
    cudaGetSymbolAddress((void**)&w2hi, g_w2hi);
    cudaGetSymbolAddress((void**)&w2lo, g_w2lo);
    cudaGetSymbolAddress((void**)&q1hi, g_q1hi);
    cudaGetSymbolAddress((void**)&q1lo, g_q1lo);
    cudaGetSymbolAddress((void**)&q2hi, g_q2hi);
    cudaGetSymbolAddress((void**)&q2lo, g_q2lo);
    cudaGetSymbolAddress((void**)&ahi,  g_ahi);
    cudaGetSymbolAddress((void**)&alo,  g_alo);

    // Weight conversions (single stream; independent of data path)
    conv_frag_w<<<6272, 256>>>(off_w1, w1hi, w1lo, IN_,  1605632);
    conv_frag_w<<<512,  256>>>(off_w2, w2hi, w2lo, DFC_, 131072);
    conv_frag_w<<<3136, 256>>>(fc1_w,  q1hi, q1lo, IN_,  802816);
    conv_frag_w<<<128,  256>>>(fc2_w,  q2hi, q2lo, FCC_, 32768);

    // 1. x -> xt
    {
        dim3 grid((H_*W_ + 31)/32, (C_ + 31)/32, B_);
        dim3 block(32, 8);
        transpose_kernel<<<grid, block>>>(x, xt);
    }
    // 2. pool (zero offsets) -> p0, convert
    pool_kernel<<<dim3(N_, OUT_), 256>>>(xt, rois, nullptr, p0);
    conv_frag_a<<<1568, 256>>>(p0, ahi, alo, IN_, 401408);

    // 3. h1 = relu(p0 @ off_w1^T + b1)  [256x1024, K=12544], S=14 (Kc16=56)
    gemm_bf16<<<dim3(8, 2, 14), 256>>>(ahi, alo, w1hi, w1lo, part, DFC_, 784, 56);
    reduce_kernel<<<(N_*DFC_/4)/256, 256>>>((const float4*)part, off_b1, (float4*)h1, DFC_/4, 14, 1);

    // 4. h2 = relu(h1 @ off_w2^T + b2)  [256x1024, K=1024], S=8 (Kc16=8)
    conv_frag_a<<<128, 256>>>(h1, ahi, alo, DFC_, 32768);
    gemm_bf16<<<dim3(8, 2, 8), 256>>>(ahi, alo, w2hi, w2lo, part, DFC_, 64, 8);
    reduce_kernel<<<(N_*DFC_/4)/256, 256>>>((const float4*)part, off_b2, (float4*)h2, DFC_/4, 8, 1);

    // 5. off = h2 @ off_w3^T + b3       [256x98]
    off3_kernel<<<N_, 256>>>(h2, off_w3, off_b3, offb);

    // 6. pool (learned offsets) -> p1, convert
    pool_kernel<<<dim3(N_, OUT_), 256>>>(xt, rois, offb, p1);
    conv_frag_a<<<1568, 256>>>(p1, ahi, alo, IN_, 401408);

    // 7. f1 = relu(p1 @ fc1_w^T + b)    [256x512, K=12544], S=28 (Kc16=28)
    gemm_bf16<<<dim3(4, 2, 28), 256>>>(ahi, alo, q1hi, q1lo, part, FCC_, 784, 28);
    reduce_kernel<<<(N_*FCC_/4)/256, 256>>>((const float4*)part, fc1_b, (float4*)f1, FCC_/4, 28, 1);

    // 8. f2 = relu(f1 @ fc2_w^T + b)    [256x512, K=512], S=16 (Kc16=2)
    conv_frag_a<<<64, 256>>>(f1, ahi, alo, FCC_, 16384);
    gemm_bf16<<<dim3(4, 2, 16), 256>>>(ahi, alo, q2hi, q2lo, part, FCC_, 32, 2);
    reduce_kernel<<<(N_*FCC_/4)/256, 256>>>((const float4*)part, fc2_b, (float4*)f2, FCC_/4, 16, 1);

    // 9. out = f2 @ box_w^T + box_b     [256x4]
    box_kernel<<<N_, 128>>>(f2, box_w, box_b, out);
}

// round 15
// speedup vs baseline: 2.8744x; 1.0225x over previous
#include <cuda_runtime.h>
#include <cuda_bf16.h>
#include <cstdint>

// Problem constants
#define B_ 8
#define C_ 256
#define H_ 25
#define W_ 25
#define N_ 256
#define OUT_ 7
#define NBIN 49
#define IN_ 12544   // C*7*7
#define DFC_ 1024
#define FCC_ 512
#define SS_ (25.0f/255.0f)
#define TRANS_STD_ 0.1f

// fp32 scratch
__device__ float g_xt[B_*H_*W_*C_];
__device__ float g_p0[N_*IN_];
__device__ float g_h2[N_*DFC_];
__device__ float g_off[N_*2*NBIN];
__device__ float g_p1[N_*IN_];
__device__ float g_f2[N_*FCC_];
__device__ float g_part[4194304];      // split-K partials (max 16*256*1024)

// bf16 hi/lo fragment-ordered buffers (uint4 = 4 regs x 2 bf16 = 8 elements)
__device__ uint4 g_w1hi[1605632], g_w1lo[1605632];   // off_w1 1024x12544
__device__ uint4 g_w2hi[131072],  g_w2lo[131072];    // off_w2 1024x1024
__device__ uint4 g_q1hi[802816],  g_q1lo[802816];    // fc1_w  512x12544
__device__ uint4 g_q2hi[32768],   g_q2lo[32768];     // fc2_w  512x512
__device__ uint4 g_ahi[401408],   g_alo[401408];     // activations (256x12544 / 8)

// ---------------------------------------------------------------------------
// Transpose x (B,C,H,W) -> xt (B,H*W,C)
// ---------------------------------------------------------------------------
__global__ void transpose_kernel(const float* __restrict__ x, float* __restrict__ xt) {
    __shared__ float tile[32][33];
    int b  = blockIdx.z;
    int s0 = blockIdx.x * 32;
    int c0 = blockIdx.y * 32;
    int tx = threadIdx.x, ty = threadIdx.y;
    const int HW = H_*W_;
    #pragma unroll
    for (int i = ty; i < 32; i += 8) {
        int c = c0 + i, s = s0 + tx;
        if (c < C_ && s < HW) tile[i][tx] = x[(b*C_ + c)*HW + s];
    }
    __syncthreads();
    #pragma unroll
    for (int i = ty; i < 32; i += 8) {
        int s = s0 + i, c = c0 + tx;
        if (s < HW && c < C_) xt[(b*HW + s)*C_ + c] = tile[tx][i];
    }
}

// ---------------------------------------------------------------------------
// Deformable ROI pool, factorized; grid (N, 7)
// ---------------------------------------------------------------------------
__global__ void pool_kernel(const float* __restrict__ xt,
                            const float* __restrict__ rois,
                            const float* __restrict__ off,
                            float* __restrict__ out) {
    int n  = blockIdx.x;
    int ph = blockIdx.y;
    int t  = threadIdx.x;

    const float* r = rois + n*5;
    int   b  = (int)r[0];
    float sw = rintf(r[1])*SS_ - 0.5f;
    float sh = rintf(r[2])*SS_ - 0.5f;
    float rw = fmaxf((rintf(r[3]) + 1.0f)*SS_ - 0.5f - sw, 0.1f);
    float rh = fmaxf((rintf(r[4]) + 1.0f)*SS_ - 0.5f - sh, 0.1f);
    float bw = rw / (float)OUT_;
    float bh = rh / (float)OUT_;

    __shared__ float s_wx[8], s_wy[8];
    __shared__ int   s_xa, s_ya, s_nx, s_ny, s_cx, s_cy;

    const int base_b = b * (H_*W_) * C_;

    for (int pw = 0; pw < OUT_; pw++) {
        int bin = ph*OUT_ + pw;
        if (t == 0) {
            float txo = off ? off[n*(2*NBIN) + bin] * TRANS_STD_ : 0.0f;
            float wstart = pw*bw + sw + txo*rw;
            int xa = 1000, xb = -1000, cx = 0;
            #pragma unroll
            for (int j = 0; j < 4; j++) {
                float sx = wstart + (float)j * (bw*0.25f);
                if (sx >= -0.5f && sx <= (float)W_ - 0.5f) {
                    cx++;
                    float xc = fminf(fmaxf(sx, 0.0f), (float)(W_-1));
                    int xi0 = (int)floorf(xc);
                    int xi1 = (int)ceilf(xc);
                    xa = min(xa, xi0); xb = max(xb, xi1);
                }
            }
            int nx = (cx > 0) ? (xb - xa + 1) : 0;
            if (nx > 8) nx = 8;
            float wl[8];
            #pragma unroll
            for (int q = 0; q < 8; q++) wl[q] = 0.0f;
            #pragma unroll
            for (int j = 0; j < 4; j++) {
                float sx = wstart + (float)j * (bw*0.25f);
                if (sx >= -0.5f && sx <= (float)W_ - 0.5f) {
                    float xc = fminf(fmaxf(sx, 0.0f), (float)(W_-1));
                    float x0 = floorf(xc);
                    float dx = xc - x0;
                    int xi0 = (int)x0;
                    int xi1 = (int)ceilf(xc);
                    wl[xi0 - xa] += 1.0f - dx;
                    if (xi1 - xa < 8) wl[xi1 - xa] += dx;
                }
            }
            s_xa = xa; s_nx = nx; s_cx = cx;
            #pragma unroll
            for (int q = 0; q < 8; q++) s_wx[q] = wl[q];
        }
        if (t == 32) {
            float tyo = off ? off[n*(2*NBIN) + NBIN + bin] * TRANS_STD_ : 0.0f;
            float hstart = ph*bh + sh + tyo*rh;
            int ya = 1000, yb = -1000, cy = 0;
            #pragma unroll
            for (int i = 0; i < 4; i++) {
                float sy = hstart + (float)i * (bh*0.25f);
                if (sy >= -0.5f && sy <= (float)H_ - 0.5f) {
                    cy++;
                    float yc = fminf(fmaxf(sy, 0.0f), (float)(H_-1));
                    int yi0 = (int)floorf(yc);
                    int yi1 = (int)ceilf(yc);
                    ya = min(ya, yi0); yb = max(yb, yi1);
                }
            }
            int ny = (cy > 0) ? (yb - ya + 1) : 0;
            if (ny > 8) ny = 8;
            float wl[8];
            #pragma unroll
            for (int q = 0; q < 8; q++) wl[q] = 0.0f;
            #pragma unroll
            for (int i = 0; i < 4; i++) {
                float sy = hstart + (float)i * (bh*0.25f);
                if (sy >= -0.5f && sy <= (float)H_ - 0.5f) {
                    float yc = fminf(fmaxf(sy, 0.0f), (float)(H_-1));
                    float y0 = floorf(yc);
                    float dy = yc - y0;
                    int yi0 = (int)y0;
                    int yi1 = (int)ceilf(yc);
                    wl[yi0 - ya] += 1.0f - dy;
                    if (yi1 - ya < 8) wl[yi1 - ya] += dy;
                }
            }
            s_ya = ya; s_ny = ny; s_cy = cy;
            #pragma unroll
            for (int q = 0; q < 8; q++) s_wy[q] = wl[q];
        }
        __syncthreads();

        float inv = 1.0f / fmaxf((float)(s_cx * s_cy), 1.0f);
        float acc = 0.0f;
        int ny = s_ny, nx = s_nx, ya = s_ya, xa = s_xa;
        for (int iy = 0; iy < ny; iy++) {
            float wy = s_wy[iy];
            if (wy == 0.0f) continue;
            int rowoff = base_b + ((ya + iy)*W_ + xa)*C_ + t;
            for (int ix = 0; ix < nx; ix++) {
                float wv = wy * s_wx[ix];
                if (wv != 0.0f) acc += wv * xt[rowoff + ix*C_];
            }
        }
        out[n*IN_ + t*NBIN + bin] = acc * inv;
        __syncthreads();
    }
}

// ---------------------------------------------------------------------------
// fp32 -> bf16 hi/lo pack
// ---------------------------------------------------------------------------
__device__ __forceinline__ void packpair(float e, float o, uint32_t& h, uint32_t& l) {
    asm("cvt.rn.bf16x2.f32 %0, %1, %2;" : "=r"(h) : "f"(o), "f"(e));
    float re = e - __uint_as_float(h << 16);
    float ro = o - __uint_as_float(h & 0xffff0000u);
    asm("cvt.rn.bf16x2.f32 %0, %1, %2;" : "=r"(l) : "f"(ro), "f"(re));
}

// ---------------------------------------------------------------------------
// Weight frag pack (B operand).  uint4 id = ((mb*KT+kt)*8+wt)*32+lane
// ---------------------------------------------------------------------------
__device__ __forceinline__ void frag_w_pack(const float* __restrict__ Wm,
                                            uint4* __restrict__ hi,
                                            uint4* __restrict__ lo,
                                            int K, int tid) {
    int lane = tid & 31;
    int rest = tid >> 5;
    int wt = rest & 7; rest >>= 3;
    int KT = K >> 4;
    int kt = rest % KT;
    int mb = rest / KT;
    int m0 = mb*128 + wt*16 + (lane >> 2);
    int k0 = kt*16 + (lane & 3)*2;
    uint4 h, l;
    const float* p00 = Wm + (size_t)m0*K + k0;
    const float* p10 = Wm + (size_t)(m0+8)*K + k0;
    packpair(p00[0], p00[1], h.x, l.x);
    packpair(p00[8], p00[9], h.y, l.y);
    packpair(p10[0], p10[1], h.z, l.z);
    packpair(p10[8], p10[9], h.w, l.w);
    hi[tid] = h; lo[tid] = l;
}

// All four weight conversions in ONE launch, range-dispatched on blockIdx.x.
// Ranges: w1 [0,6272)  w2 [6272,6784)  q1 [6784,9920)  q2 [9920,10048)
__global__ void conv_frag_w_all(
    const float* __restrict__ w1, const float* __restrict__ w2,
    const float* __restrict__ q1, const float* __restrict__ q2,
    uint4* __restrict__ w1h, uint4* __restrict__ w1l,
    uint4* __restrict__ w2h, uint4* __restrict__ w2l,
    uint4* __restrict__ q1h, uint4* __restrict__ q1l,
    uint4* __restrict__ q2h, uint4* __restrict__ q2l) {
    int bid = blockIdx.x;
    int t = threadIdx.x;
    if (bid < 6272)       frag_w_pack(w1, w1h, w1l, IN_,  bid*256 + t);
    else if (bid < 6784)  frag_w_pack(w2, w2h, w2l, DFC_, (bid-6272)*256 + t);
    else if (bid < 9920)  frag_w_pack(q1, q1h, q1l, IN_,  (bid-6784)*256 + t);
    else                  frag_w_pack(q2, q2h, q2l, FCC_, (bid-9920)*256 + t);
}

// ---------------------------------------------------------------------------
// Activation -> fragment-ordered bf16 hi/lo (from fp32 array)
// ---------------------------------------------------------------------------
__global__ void conv_frag_a(const float* __restrict__ A, uint4* __restrict__ hi,
                            uint4* __restrict__ lo, int K, int total) {
    int tid = blockIdx.x * 256 + threadIdx.x;
    if (tid >= total) return;
    int lane = tid & 31;
    int rest = tid >> 5;
    int at = rest & 7; rest >>= 3;
    int KT = K >> 4;
    int kt = rest % KT;
    int nb = rest / KT;
    int m0 = nb*128 + at*16 + (lane >> 2);
    int k0 = kt*16 + (lane & 3)*2;
    uint4 h, l;
    const float* p00 = A + (size_t)m0*K + k0;
    const float* p10 = A + (size_t)(m0+8)*K + k0;
    packpair(p00[0], p00[1], h.x, l.x);
    packpair(p10[0], p10[1], h.y, l.y);
    packpair(p00[8], p00[9], h.z, l.z);
    packpair(p10[8], p10[9], h.w, l.w);
    hi[tid] = h; lo[tid] = l;
}

// ---------------------------------------------------------------------------
// Fused: split-K reduce + bias + ReLU + fragment pack (for activations that
// ONLY feed another GEMM — no fp32 output needed).
// grid: (N_*M/8)/256 blocks.
// ---------------------------------------------------------------------------
__global__ void reduce_frag(const float* __restrict__ part,
                            const float* __restrict__ bias,
                            uint4* __restrict__ hi, uint4* __restrict__ lo,
                            int M, int S) {
    int tid = blockIdx.x * 256 + threadIdx.x;
    int lane = tid & 31;
    int rest = tid >> 5;
    int at = rest & 7; rest >>= 3;
    int KT = M >> 4;
    int kt = rest % KT;
    int nb = rest / KT;
    int m0 = nb*128 + at*16 + (lane >> 2);
    int k0 = kt*16 + (lane & 3)*2;

    float2 bb0 = *(const float2*)(bias + k0);
    float2 bb8 = *(const float2*)(bias + k0 + 8);
    float a00 = bb0.x, a01 = bb0.y, a08 = bb8.x, a09 = bb8.y;   // row m0
    float b00 = bb0.x, b01 = bb0.y, b08 = bb8.x, b09 = bb8.y;   // row m0+8

    const float* p0 = part + (size_t)m0*M + k0;
    const float* p1 = part + (size_t)(m0+8)*M + k0;
    size_t stride = (size_t)N_ * M;
    for (int s = 0; s < S; s++) {
        float2 v;
        v = *(const float2*)(p0 + s*stride);     a00 += v.x; a01 += v.y;
        v = *(const float2*)(p0 + s*stride + 8); a08 += v.x; a09 += v.y;
        v = *(const float2*)(p1 + s*stride);     b00 += v.x; b01 += v.y;
        v = *(const float2*)(p1 + s*stride + 8); b08 += v.x; b09 += v.y;
    }
    a00 = fmaxf(a00, 0.0f); a01 = fmaxf(a01, 0.0f);
    a08 = fmaxf(a08, 0.0f); a09 = fmaxf(a09, 0.0f);
    b00 = fmaxf(b00, 0.0f); b01 = fmaxf(b01, 0.0f);
    b08 = fmaxf(b08, 0.0f); b09 = fmaxf(b09, 0.0f);

    uint4 h, l;
    packpair(a00, a01, h.x, l.x);   // (m0,   k0..k0+1)
    packpair(b00, b01, h.y, l.y);   // (m0+8, k0..k0+1)
    packpair(a08, a09, h.z, l.z);   // (m0,   k0+8..k0+9)
    packpair(b08, b09, h.w, l.w);   // (m0+8, k0+8..k0+9)
    hi[tid] = h; lo[tid] = l;
}

// ---------------------------------------------------------------------------
// bf16 3-term mma.sync GEMM, split-K, cp.async double-buffered smem staging.
// ---------------------------------------------------------------------------
__device__ __forceinline__ void mma_bf16(float* c, const uint4& a,
                                         uint32_t b0, uint32_t b1) {
    asm volatile(
        "mma.sync.aligned.m16n8k16.row.col.f32.bf16.bf16.f32 "
        "{%0,%1,%2,%3}, {%4,%5,%6,%7}, {%8,%9}, {%0,%1,%2,%3};"
        : "+f"(c[0]), "+f"(c[1]), "+f"(c[2]), "+f"(c[3])
        : "r"(a.x), "r"(a.y), "r"(a.z), "r"(a.w), "r"(b0), "r"(b1));
}

__device__ __forceinline__ void cp16(void* smem, const void* g) {
    uint32_t s = (uint32_t)__cvta_generic_to_shared(smem);
    asm volatile("cp.async.cg.shared.global [%0], [%1], 16;" :: "r"(s), "l"(g));
}
__device__ __forceinline__ void cp_commit() {
    asm volatile("cp.async.commit_group;" ::: "memory");
}
__device__ __forceinline__ void cp_wait1() {
    asm volatile("cp.async.wait_group 1;" ::: "memory");
}
__device__ __forceinline__ void cp_wait0() {
    asm volatile("cp.async.wait_group 0;" ::: "memory");
}

__global__ __launch_bounds__(256, 2) void gemm_bf16(
    const uint4* __restrict__ Ahi, const uint4* __restrict__ Alo,
    const uint4* __restrict__ Whi, const uint4* __restrict__ Wlo,
    float* __restrict__ part, int M, int KT, int Kc16) {
    __shared__ uint4 sAh[2][256], sAl[2][256], sWh[2][256], sWl[2][256];

    int tid = threadIdx.x, wid = tid >> 5, lane = tid & 31;
    int wr = wid >> 1, wc = wid & 1;
    int mb = blockIdx.x, nb = blockIdx.y, s = blockIdx.z;

    float acc[2][8][4];
    #pragma unroll
    for (int i = 0; i < 2; i++)
        #pragma unroll
        for (int j = 0; j < 8; j++)
            #pragma unroll
            for (int q = 0; q < 4; q++) acc[i][j][q] = 0.0f;

    int kt0 = s * Kc16;
    int at0 = wr*2;

    {
        size_t a_off = ((size_t)(nb*KT + kt0)*8)*32 + tid;
        size_t w_off = ((size_t)(mb*KT + kt0)*8)*32 + tid;
        cp16(&sAh[0][tid], Ahi + a_off);
        cp16(&sAl[0][tid], Alo + a_off);
        cp16(&sWh[0][tid], Whi + w_off);
        cp16(&sWl[0][tid], Wlo + w_off);
        cp_commit();
    }

    for (int t = 0; t < Kc16; t++) {
        int buf = t & 1;
        if (t + 1 < Kc16) {
            int kt = kt0 + t + 1;
            int nbuf = (t + 1) & 1;
            size_t a_off = ((size_t)(nb*KT + kt)*8)*32 + tid;
            size_t w_off = ((size_t)(mb*KT + kt)*8)*32 + tid;
            cp16(&sAh[nbuf][tid], Ahi + a_off);
            cp16(&sAl[nbuf][tid], Alo + a_off);
            cp16(&sWh[nbuf][tid], Whi + w_off);
            cp16(&sWl[nbuf][tid], Wlo + w_off);
            cp_commit();
            cp_wait1();
        } else {
            cp_wait0();
        }
        __syncthreads();

        uint4 ah0 = sAh[buf][at0*32 + lane];
        uint4 ah1 = sAh[buf][at0*32 + 32 + lane];
        uint4 al0 = sAl[buf][at0*32 + lane];
        uint4 al1 = sAl[buf][at0*32 + 32 + lane];
        #pragma unroll
        for (int wt = 0; wt < 4; wt++) {
            uint4 wh = sWh[buf][wc*128 + wt*32 + lane];
            uint4 wl = sWl[buf][wc*128 + wt*32 + lane];
            int nf = wt*2;
            mma_bf16(acc[0][nf],   ah0, wh.x, wh.y);
            mma_bf16(acc[0][nf+1], ah0, wh.z, wh.w);
            mma_bf16(acc[1][nf],   ah1, wh.x, wh.y);
            mma_bf16(acc[1][nf+1], ah1, wh.z, wh.w);
            mma_bf16(acc[0][nf],   ah0, wl.x, wl.y);
            mma_bf16(acc[0][nf+1], ah0, wl.z, wl.w);
            mma_bf16(acc[1][nf],   ah1, wl.x, wl.y);
            mma_bf16(acc[1][nf+1], ah1, wl.z, wl.w);
            mma_bf16(acc[0][nf],   al0, wh.x, wh.y);
            mma_bf16(acc[0][nf+1], al0, wh.z, wh.w);
            mma_bf16(acc[1][nf],   al1, wh.x, wh.y);
            mma_bf16(acc[1][nf+1], al1, wh.z, wh.w);
        }
        __syncthreads();
    }

    float* p = part + (size_t)s * N_ * M;
    #pragma unroll
    for (int i = 0; i < 2; i++) {
        int row = nb*128 + wr*32 + i*16 + (lane >> 2);
        #pragma unroll
        for (int nf = 0; nf < 8; nf++) {
            int col = mb*128 + wc*64 + nf*8 + (lane & 3)*2;
            *(float2*)(p + (size_t)row*M + col)     = make_float2(acc[i][nf][0], acc[i][nf][1]);
            *(float2*)(p + (size_t)(row+8)*M + col) = make_float2(acc[i][nf][2], acc[i][nf][3]);
        }
    }
}

// ---------------------------------------------------------------------------
// Reduce split-K partials + bias (+ optional relu), float4 (fp32 output path)
// ---------------------------------------------------------------------------
__global__ void reduce_kernel(const float4* __restrict__ part,
                              const float* __restrict__ bias,
                              float4* __restrict__ C, int M4, int S, int relu) {
    int idx = blockIdx.x * 256 + threadIdx.x;
    int col4 = idx % M4;
    const float4* bp = (const float4*)bias;
    float4 acc = bp[col4];
    for (int s = 0; s < S; s++) {
        float4 v = part[(size_t)s*N_*M4 + idx];
        acc.x += v.x; acc.y += v.y; acc.z += v.z; acc.w += v.w;
    }
    if (relu) {
        acc.x = fmaxf(acc.x, 0.0f); acc.y = fmaxf(acc.y, 0.0f);
        acc.z = fmaxf(acc.z, 0.0f); acc.w = fmaxf(acc.w, 0.0f);
    }
    C[idx] = acc;
}

// ---------------------------------------------------------------------------
// off3 head
// ---------------------------------------------------------------------------
__global__ void off3_kernel(const float* __restrict__ h,
                            const float* __restrict__ w3,
                            const float* __restrict__ b3,
                            float* __restrict__ out) {
    int n = blockIdx.x;
    int tid = threadIdx.x;
    __shared__ float sh[DFC_];
    ((float4*)sh)[tid] = ((const float4*)(h + n*DFC_))[tid];
    __syncthreads();
    int warp = tid >> 5, lane = tid & 31;
    for (int o = warp; o < 2*NBIN; o += 8) {
        const float4* w = (const float4*)(w3 + o*DFC_);
        float acc = 0.0f;
        #pragma unroll
        for (int i = lane; i < DFC_/4; i += 32) {
            float4 wv = w[i];
            float4 av = ((const float4*)sh)[i];
            acc += wv.x*av.x + wv.y*av.y + wv.z*av.z + wv.w*av.w;
        }
        #pragma unroll
        for (int d = 16; d > 0; d >>= 1) acc += __shfl_down_sync(0xffffffffu, acc, d);
        if (lane == 0) out[n*(2*NBIN) + o] = acc + b3[o];
    }
}

// ---------------------------------------------------------------------------
// box head
// ---------------------------------------------------------------------------
__global__ void box_kernel(const float* __restrict__ f2,
                           const float* __restrict__ bw,
                           const float* __restrict__ bb,
                           float* __restrict__ out) {
    int n = blockIdx.x;
    int w = threadIdx.x >> 5;
    int lane = threadIdx.x & 31;
    float acc = 0.0f;
    for (int k = lane; k < FCC_; k += 32) acc += f2[n*FCC_ + k]*bw[w*FCC_ + k];
    #pragma unroll
    for (int o = 16; o > 0; o >>= 1) acc += __shfl_down_sync(0xffffffffu, acc, o);
    if (lane == 0) out[n*4 + w] = acc + bb[w];
}

// ---------------------------------------------------------------------------
extern "C" void kernel_launch(void* const* d_in, const int* in_sizes, int n_in,
                              void* d_out, int out_size) {
    const float* x      = (const float*)d_in[0];
    const float* rois   = (const float*)d_in[1];
    const float* off_w1 = (const float*)d_in[2];
    const float* off_b1 = (const float*)d_in[3];
    const float* off_w2 = (const float*)d_in[4];
    const float* off_b2 = (const float*)d_in[5];
    const float* off_w3 = (const float*)d_in[6];
    const float* off_b3 = (const float*)d_in[7];
    const float* fc1_w  = (const float*)d_in[8];
    const float* fc1_b  = (const float*)d_in[9];
    const float* fc2_w  = (const float*)d_in[10];
    const float* fc2_b  = (const float*)d_in[11];
    const float* box_w  = (const float*)d_in[12];
    const float* box_b  = (const float*)d_in[13];
    float* out = (float*)d_out;

    float *xt, *p0, *h2, *offb, *p1, *f2, *part;
    uint4 *w1hi, *w1lo, *w2hi, *w2lo, *q1hi, *q1lo, *q2hi, *q2lo, *ahi, *alo;
    cudaGetSymbolAddress((void**)&xt,   g_xt);
    cudaGetSymbolAddress((void**)&p0,   g_p0);
    cudaGetSymbolAddress((void**)&h2,   g_h2);
    cudaGetSymbolAddress((void**)&offb, g_off);
    cudaGetSymbolAddress((void**)&p1,   g_p1);
    cudaGetSymbolAddress((void**)&f2,   g_f2);
    cudaGetSymbolAddress((void**)&part, g_part);
    cudaGetSymbolAddress((void**)&w1hi, g_w1hi);
    cudaGetSymbolAddress((void**)&w1lo, g_w1lo);
    cudaGetSymbolAddress((void**)&w2hi, g_w2hi);
    cudaGetSymbolAddress((void**)&w2lo, g_w2lo);
    cudaGetSymbolAddress((void**)&q1hi, g_q1hi);
    cudaGetSymbolAddress((void**)&q1lo, g_q1lo);
    cudaGetSymbolAddress((void**)&q2hi, g_q2hi);
    cudaGetSymbolAddress((void**)&q2lo, g_q2lo);
    cudaGetSymbolAddress((void**)&ahi,  g_ahi);
    cudaGetSymbolAddress((void**)&alo,  g_alo);

    // 0. All weight conversions, one launch
    conv_frag_w_all<<<10048, 256>>>(off_w1, off_w2, fc1_w, fc2_w,
                                    w1hi, w1lo, w2hi, w2lo,
                                    q1hi, q1lo, q2hi, q2lo);

    // 1. x -> xt
    {
        dim3 grid((H_*W_ + 31)/32, (C_ + 31)/32, B_);
        dim3 block(32, 8);
        transpose_kernel<<<grid, block>>>(x, xt);
    }
    // 2. pool (zero offsets) -> p0, convert
    pool_kernel<<<dim3(N_, OUT_), 256>>>(xt, rois, nullptr, p0);
    conv_frag_a<<<1568, 256>>>(p0, ahi, alo, IN_, 401408);

    // 3. h1 frags = relu(p0 @ off_w1^T + b1)  [256x1024, K=12544], S=16 (Kc16=49)
    gemm_bf16<<<dim3(8, 2, 16), 256>>>(ahi, alo, w1hi, w1lo, part, DFC_, 784, 49);
    reduce_frag<<<128, 256>>>(part, off_b1, ahi, alo, DFC_, 16);

    // 4. h2 = relu(h1 @ off_w2^T + b2)  [256x1024, K=1024], S=8 (Kc16=8)
    gemm_bf16<<<dim3(8, 2, 8), 256>>>(ahi, alo, w2hi, w2lo, part, DFC_, 64, 8);
    reduce_kernel<<<(N_*DFC_/4)/256, 256>>>((const float4*)part, off_b2, (float4*)h2, DFC_/4, 8, 1);

    // 5. off = h2 @ off_w3^T + b3       [256x98]
    off3_kernel<<<N_, 256>>>(h2, off_w3, off_b3, offb);

    // 6. pool (learned offsets) -> p1, convert
    pool_kernel<<<dim3(N_, OUT_), 256>>>(xt, rois, offb, p1);
    conv_frag_a<<<1568, 256>>>(p1, ahi, alo, IN_, 401408);

    // 7. f1 frags = relu(p1 @ fc1_w^T + b)  [256x512, K=12544], S=28 (Kc16=28)
    gemm_bf16<<<dim3(4, 2, 28), 256>>>(ahi, alo, q1hi, q1lo, part, FCC_, 784, 28);
    reduce_frag<<<64, 256>>>(part, fc1_b, ahi, alo, FCC_, 28);

    // 8. f2 = relu(f1 @ fc2_w^T + b)    [256x512, K=512], S=16 (Kc16=2)
    gemm_bf16<<<dim3(4, 2, 16), 256>>>(ahi, alo, q2hi, q2lo, part, FCC_, 32, 2);
    reduce_kernel<<<(N_*FCC_/4)/256, 256>>>((const float4*)part, fc2_b, (float4*)f2, FCC_/4, 16, 1);

    // 9. out = f2 @ box_w^T + box_b     [256x4]
    box_kernel<<<N_, 128>>>(f2, box_w, box_b, out);
}